// round 6
// baseline (speedup 1.0000x reference)
#include <cuda_runtime.h>
#include <cuda_bf16.h>
#include <mma.h>
#include <cstddef>
#include <cstdint>

using namespace nvcuda;

#define B 16
#define S 1024
#define D 384
#define QK 64

// bf16 hi/lo split operands
__device__ __nv_bfloat16 g_Qhi[(size_t)B * S * QK];
__device__ __nv_bfloat16 g_Qlo[(size_t)B * S * QK];
__device__ __nv_bfloat16 g_Khi[(size_t)B * S * QK];
__device__ __nv_bfloat16 g_Klo[(size_t)B * S * QK];
__device__ __nv_bfloat16 g_XThi[(size_t)B * D * S];   // [b][c][m]
__device__ __nv_bfloat16 g_XTlo[(size_t)B * D * S];
__device__ __nv_bfloat16 g_Phi[(size_t)B * S * S];    // softmax probs hi
__device__ __nv_bfloat16 g_Plo[(size_t)B * S * S];

#define CP_ASYNC16(dst_u32, src_ptr) \
    asm volatile("cp.async.cg.shared.global [%0], [%1], 16;\n" :: "r"(dst_u32), "l"(src_ptr))
#define CP_COMMIT() asm volatile("cp.async.commit_group;\n" ::)
#define CP_WAIT2()  asm volatile("cp.async.wait_group 2;\n" ::)
#define CP_WAIT1()  asm volatile("cp.async.wait_group 1;\n" ::)
#define CP_WAIT0()  asm volatile("cp.async.wait_group 0;\n" ::)

// smem tile: 128 rows x 64 bf16, pitch 72 bf16 (144B)
#define PITCH 72
#define MAT_BYTES (128 * PITCH * 2)   // 18432

typedef wmma::fragment<wmma::matrix_a, 16, 16, 16, __nv_bfloat16, wmma::row_major> FragA;
typedef wmma::fragment<wmma::matrix_b, 16, 16, 16, __nv_bfloat16, wmma::col_major> FragB;
typedef wmma::fragment<wmma::accumulator, 16, 16, 16, float> FragC;

// ---------------------------------------------------------------------------
// Kernel 1: per-position Q/K projection -> bf16 hi/lo
// ---------------------------------------------------------------------------
__global__ __launch_bounds__(256) void proj_kernel(
    const float* __restrict__ x, const float* __restrict__ qw,
    const float* __restrict__ qb, const float* __restrict__ kw)
{
    const int n = blockIdx.x;
    __shared__ float xs[B][D + 1];

    const int tid = threadIdx.x;
    for (int idx = tid; idx < B * D; idx += 256) {
        int b = idx / D, c = idx % D;
        xs[b][c] = x[((size_t)b * S + n) * D + c];
    }
    __syncthreads();

    const int lane = tid & 31;
    const int wid  = tid >> 5;
    const int b    = lane & 15;
    const int half = lane >> 4;
    const float scale = 0.05103103630798287f;  // 384^-0.5

    #pragma unroll
    for (int s = 0; s < 8; s++) {
        const int gidx = (wid * 8 + s) * 2 + half;
        const bool isq = (gidx < 64);
        const int d = isq ? gidx : gidx - 64;
        const float* w = isq ? qw : kw;
        const float4* wp = (const float4*)(w + ((size_t)n * QK + d) * D);

        float a0 = 0.f, a1 = 0.f, a2 = 0.f, a3 = 0.f;
        #pragma unroll 8
        for (int c4 = 0; c4 < D / 4; c4++) {
            float4 wv = __ldg(wp + c4);
            int c = c4 * 4;
            a0 += xs[b][c + 0] * wv.x;
            a1 += xs[b][c + 1] * wv.y;
            a2 += xs[b][c + 2] * wv.z;
            a3 += xs[b][c + 3] * wv.w;
        }
        float acc = (a0 + a1) + (a2 + a3);

        const size_t o = ((size_t)b * S + n) * QK + d;
        if (isq) {
            float qv = scale * (acc + qb[n * QK + d]);
            __nv_bfloat16 h = __float2bfloat16(qv);
            g_Qhi[o] = h;
            g_Qlo[o] = __float2bfloat16(qv - __bfloat162float(h));
        } else {
            __nv_bfloat16 h = __float2bfloat16(acc);
            g_Khi[o] = h;
            g_Klo[o] = __float2bfloat16(acc - __bfloat162float(h));
        }
    }
}

// ---------------------------------------------------------------------------
// Kernel 1b: transpose+split x -> XT[b][c][m] bf16 hi/lo
// ---------------------------------------------------------------------------
__global__ __launch_bounds__(256) void xsplit_kernel(const float* __restrict__ x)
{
    __shared__ float tb[32][33];
    const int b = blockIdx.z, m0 = blockIdx.x * 32, c0 = blockIdx.y * 32;
    const int tx = threadIdx.x, ty = threadIdx.y;

    #pragma unroll
    for (int j = 0; j < 4; j++)
        tb[ty + 8 * j][tx] = x[((size_t)b * S + m0 + ty + 8 * j) * D + c0 + tx];
    __syncthreads();
    #pragma unroll
    for (int j = 0; j < 4; j++) {
        float v = tb[tx][ty + 8 * j];
        size_t o = ((size_t)b * D + c0 + ty + 8 * j) * S + m0 + tx;
        __nv_bfloat16 h = __float2bfloat16(v);
        g_XThi[o] = h;
        g_XTlo[o] = __float2bfloat16(v - __bfloat162float(h));
    }
}

// ---------------------------------------------------------------------------
// Kernel 2: logits row-strip. Grid=128 (b,nt). Q resident, 8 K-tiles streamed
// through 3-buffer cp.async pipeline. smem = 36864 + 3*36864 = 147456.
// ---------------------------------------------------------------------------
__global__ __launch_bounds__(256) void logits_mma(
    const float* __restrict__ attn_bias, float* __restrict__ attn)
{
    extern __shared__ __nv_bfloat16 sm[];
    // layout: Qh[128][72], Ql, then 3 K buffers of (Kh, Kl)
    __nv_bfloat16* Qh = sm;
    __nv_bfloat16* Ql = sm + 128 * PITCH;

    const int tid = threadIdx.x;
    const int bx = blockIdx.x;
    const int nt = bx & 7, b = bx >> 3;
    const int n0 = nt * 128;

    const uint32_t smb = (uint32_t)__cvta_generic_to_shared(sm);
    const __nv_bfloat16* qhp = g_Qhi + ((size_t)b * S + n0) * QK;
    const __nv_bfloat16* qlp = g_Qlo + ((size_t)b * S + n0) * QK;
    const __nv_bfloat16* khp = g_Khi + (size_t)b * S * QK;
    const __nv_bfloat16* klp = g_Klo + (size_t)b * S * QK;

    // K-tile loader: tile mt into buffer bufj
    #define LOAD_K(mt_, bufj_) do { \
        const uint32_t kb_ = smb + 2u * (uint32_t)MAT_BYTES + (uint32_t)(bufj_) * 2u * MAT_BYTES; \
        const __nv_bfloat16* kh_ = khp + (size_t)(mt_) * 128 * QK; \
        const __nv_bfloat16* kl_ = klp + (size_t)(mt_) * 128 * QK; \
        _Pragma("unroll") \
        for (int i = 0; i < 4; i++) { \
            int g = tid + 256 * i; \
            int r = g >> 3, c16 = g & 7; \
            CP_ASYNC16(kb_ + (uint32_t)(r * 144 + c16 * 16), kh_ + (size_t)r * QK + c16 * 8); \
            CP_ASYNC16(kb_ + (uint32_t)MAT_BYTES + (uint32_t)(r * 144 + c16 * 16), \
                       kl_ + (size_t)r * QK + c16 * 8); \
        } \
    } while (0)

    // prologue: Q + K0 (group0), K1 (group1)
    #pragma unroll
    for (int i = 0; i < 4; i++) {
        int g = tid + 256 * i;
        int r = g >> 3, c16 = g & 7;
        CP_ASYNC16(smb + (uint32_t)(r * 144 + c16 * 16), qhp + (size_t)r * QK + c16 * 8);
        CP_ASYNC16(smb + (uint32_t)MAT_BYTES + (uint32_t)(r * 144 + c16 * 16),
                   qlp + (size_t)r * QK + c16 * 8);
    }
    LOAD_K(0, 0); CP_COMMIT();
    LOAD_K(1, 1); CP_COMMIT();

    const int wid = tid >> 5;
    const int wn = wid >> 2;     // 0..1
    const int wm = wid & 3;      // 0..3

    for (int mt = 0; mt < 8; mt++) {
        __syncthreads();                       // all warps done with tile mt-1
        if (mt + 2 < 8) { LOAD_K(mt + 2, (mt + 2) % 3); CP_COMMIT(); }
        if (mt < 6)      CP_WAIT2();
        else if (mt == 6) CP_WAIT1();
        else             CP_WAIT0();
        __syncthreads();

        const __nv_bfloat16* Kh = sm + 2 * 128 * PITCH + (size_t)(mt % 3) * 2 * 128 * PITCH;
        const __nv_bfloat16* Kl = Kh + 128 * PITCH;
        const int m0 = mt * 128;

        FragC acc[4][2];
        #pragma unroll
        for (int i = 0; i < 4; i++)
            #pragma unroll
            for (int j = 0; j < 2; j++) wmma::fill_fragment(acc[i][j], 0.0f);

        #pragma unroll
        for (int kk = 0; kk < 4; kk++) {
            FragA ah[4], al[4];
            FragB bh[2], bl[2];
            #pragma unroll
            for (int i = 0; i < 4; i++) {
                int r = wn * 64 + i * 16;
                wmma::load_matrix_sync(ah[i], Qh + r * PITCH + kk * 16, PITCH);
                wmma::load_matrix_sync(al[i], Ql + r * PITCH + kk * 16, PITCH);
            }
            #pragma unroll
            for (int j = 0; j < 2; j++) {
                int c = wm * 32 + j * 16;
                wmma::load_matrix_sync(bh[j], Kh + c * PITCH + kk * 16, PITCH);
                wmma::load_matrix_sync(bl[j], Kl + c * PITCH + kk * 16, PITCH);
            }
            #pragma unroll
            for (int i = 0; i < 4; i++)
                #pragma unroll
                for (int j = 0; j < 2; j++) {
                    wmma::mma_sync(acc[i][j], ah[i], bh[j], acc[i][j]);
                    wmma::mma_sync(acc[i][j], ah[i], bl[j], acc[i][j]);
                    wmma::mma_sync(acc[i][j], al[i], bh[j], acc[i][j]);
                }
        }

        #pragma unroll
        for (int i = 0; i < 4; i++) {
            const int row = n0 + wn * 64 + i * 16;
            #pragma unroll
            for (int j = 0; j < 2; j++) {
                const int col = m0 + wm * 32 + j * 16;
                FragC bias;
                wmma::load_matrix_sync(bias, attn_bias + (size_t)row * S + col, S,
                                       wmma::mem_row_major);
                #pragma unroll
                for (int e = 0; e < bias.num_elements; e++)
                    acc[i][j].x[e] += bias.x[e];
                wmma::store_matrix_sync(attn + ((size_t)b * S + row) * S + col,
                                        acc[i][j], S, wmma::mem_row_major);
            }
        }
    }
    #undef LOAD_K
}

// ---------------------------------------------------------------------------
// Kernel 3: row softmax; writes fp32 probs + bf16 hi/lo copies
// ---------------------------------------------------------------------------
__global__ __launch_bounds__(256) void softmax_kernel(float* __restrict__ attn)
{
    const size_t rowoff = (size_t)blockIdx.x * S;
    float4* p = (float4*)(attn + rowoff);
    const int tid = threadIdx.x;
    const int lane = tid & 31, w = tid >> 5;

    float4 v = p[tid];
    float m = fmaxf(fmaxf(v.x, v.y), fmaxf(v.z, v.w));
    #pragma unroll
    for (int o = 16; o > 0; o >>= 1) m = fmaxf(m, __shfl_xor_sync(0xffffffffu, m, o));

    __shared__ float redm[8];
    __shared__ float reds[8];
    if (lane == 0) redm[w] = m;
    __syncthreads();
    m = redm[0];
    #pragma unroll
    for (int i = 1; i < 8; i++) m = fmaxf(m, redm[i]);

    float e0 = __expf(v.x - m), e1 = __expf(v.y - m);
    float e2 = __expf(v.z - m), e3 = __expf(v.w - m);
    float ssum = (e0 + e1) + (e2 + e3);
    #pragma unroll
    for (int o = 16; o > 0; o >>= 1) ssum += __shfl_xor_sync(0xffffffffu, ssum, o);
    if (lane == 0) reds[w] = ssum;
    __syncthreads();
    ssum = reds[0];
    #pragma unroll
    for (int i = 1; i < 8; i++) ssum += reds[i];

    const float inv = 1.0f / ssum;
    float v0 = e0 * inv, v1 = e1 * inv, v2 = e2 * inv, v3 = e3 * inv;
    float4 o4 = {v0, v1, v2, v3};
    p[tid] = o4;

    __nv_bfloat16 h0 = __float2bfloat16(v0), h1 = __float2bfloat16(v1);
    __nv_bfloat16 h2 = __float2bfloat16(v2), h3 = __float2bfloat16(v3);
    float l0 = v0 - __bfloat162float(h0), l1 = v1 - __bfloat162float(h1);
    float l2 = v2 - __bfloat162float(h2), l3 = v3 - __bfloat162float(h3);
    __nv_bfloat16 g0 = __float2bfloat16(l0), g1 = __float2bfloat16(l1);
    __nv_bfloat16 g2 = __float2bfloat16(l2), g3 = __float2bfloat16(l3);

    unsigned hi0 = (unsigned)__bfloat16_as_ushort(h0) | ((unsigned)__bfloat16_as_ushort(h1) << 16);
    unsigned hi1 = (unsigned)__bfloat16_as_ushort(h2) | ((unsigned)__bfloat16_as_ushort(h3) << 16);
    unsigned lo0 = (unsigned)__bfloat16_as_ushort(g0) | ((unsigned)__bfloat16_as_ushort(g1) << 16);
    unsigned lo1 = (unsigned)__bfloat16_as_ushort(g2) | ((unsigned)__bfloat16_as_ushort(g3) << 16);
    *(uint2*)&g_Phi[rowoff + (size_t)tid * 4] = make_uint2(hi0, hi1);
    *(uint2*)&g_Plo[rowoff + (size_t)tid * 4] = make_uint2(lo0, lo1);
}

// ---------------------------------------------------------------------------
// Kernel 4: out = P @ x. Grid=128 (b,nt), 3 ct tiles per block (P L2-hot),
// 16 K-chunks of 64, 3-stage cp.async pipeline. smem = 3*73728 = 221184.
// ---------------------------------------------------------------------------
__global__ __launch_bounds__(256) void out_mma(float* __restrict__ out)
{
    extern __shared__ __nv_bfloat16 sm[];

    const int tid = threadIdx.x;
    const int bx = blockIdx.x;
    const int nt = bx & 7, b = bx >> 3;
    const int n0 = nt * 128;

    const uint32_t smb = (uint32_t)__cvta_generic_to_shared(sm);
    const __nv_bfloat16* aHp = g_Phi + ((size_t)b * S + n0) * S;
    const __nv_bfloat16* aLp = g_Plo + ((size_t)b * S + n0) * S;

    const int wid = tid >> 5;
    const int wn = wid >> 2;
    const int wc = wid & 3;

    for (int ct = 0; ct < 3; ct++) {
        const int c0 = ct * 128;
        const __nv_bfloat16* bHp = g_XThi + ((size_t)b * D + c0) * S;
        const __nv_bfloat16* bLp = g_XTlo + ((size_t)b * D + c0) * S;
        const __nv_bfloat16* srcs[4] = {aHp, aLp, bHp, bLp};

        #define LOAD_CHUNK(kc_, bufj_) do { \
            const int kof_ = (kc_) * 64; \
            const uint32_t bb_ = smb + (uint32_t)(bufj_) * (4u * MAT_BYTES); \
            _Pragma("unroll") \
            for (int mtx = 0; mtx < 4; mtx++) { \
                const __nv_bfloat16* src = srcs[mtx] + kof_; \
                const uint32_t dst = bb_ + (uint32_t)mtx * MAT_BYTES; \
                _Pragma("unroll") \
                for (int i = 0; i < 4; i++) { \
                    int g = tid + 256 * i; \
                    int r = g >> 3, c16 = g & 7; \
                    CP_ASYNC16(dst + (uint32_t)(r * 144 + c16 * 16), \
                               src + (size_t)r * S + c16 * 8); \
                } \
            } \
        } while (0)

        __syncthreads();   // previous ct's compute fully done before reuse
        LOAD_CHUNK(0, 0); CP_COMMIT();
        LOAD_CHUNK(1, 1); CP_COMMIT();

        FragC acc[4][2];
        #pragma unroll
        for (int i = 0; i < 4; i++)
            #pragma unroll
            for (int j = 0; j < 2; j++) wmma::fill_fragment(acc[i][j], 0.0f);

        for (int kc = 0; kc < 16; kc++) {
            __syncthreads();
            if (kc + 2 < 16) { LOAD_CHUNK(kc + 2, (kc + 2) % 3); CP_COMMIT(); }
            if (kc < 14)      CP_WAIT2();
            else if (kc == 14) CP_WAIT1();
            else              CP_WAIT0();
            __syncthreads();

            const __nv_bfloat16* base = sm + (size_t)(kc % 3) * (4 * 128 * PITCH);
            const __nv_bfloat16* Ah = base;
            const __nv_bfloat16* Al = base + 128 * PITCH;
            const __nv_bfloat16* Bh = base + 2 * 128 * PITCH;
            const __nv_bfloat16* Bl = base + 3 * 128 * PITCH;

            #pragma unroll
            for (int kk = 0; kk < 4; kk++) {
                FragA ah[4], al[4];
                FragB bh[2], bl[2];
                #pragma unroll
                for (int i = 0; i < 4; i++) {
                    int r = wn * 64 + i * 16;
                    wmma::load_matrix_sync(ah[i], Ah + r * PITCH + kk * 16, PITCH);
                    wmma::load_matrix_sync(al[i], Al + r * PITCH + kk * 16, PITCH);
                }
                #pragma unroll
                for (int j = 0; j < 2; j++) {
                    int c = wc * 32 + j * 16;
                    wmma::load_matrix_sync(bh[j], Bh + c * PITCH + kk * 16, PITCH);
                    wmma::load_matrix_sync(bl[j], Bl + c * PITCH + kk * 16, PITCH);
                }
                #pragma unroll
                for (int i = 0; i < 4; i++)
                    #pragma unroll
                    for (int j = 0; j < 2; j++) {
                        wmma::mma_sync(acc[i][j], ah[i], bh[j], acc[i][j]);
                        wmma::mma_sync(acc[i][j], ah[i], bl[j], acc[i][j]);
                        wmma::mma_sync(acc[i][j], al[i], bh[j], acc[i][j]);
                    }
            }
        }

        #pragma unroll
        for (int i = 0; i < 4; i++) {
            const int row = n0 + wn * 64 + i * 16;
            #pragma unroll
            for (int j = 0; j < 2; j++) {
                const int col = c0 + wc * 32 + j * 16;
                wmma::store_matrix_sync(out + ((size_t)b * S + row) * D + col,
                                        acc[i][j], D, wmma::mem_row_major);
            }
        }
        #undef LOAD_CHUNK
    }
}

// ---------------------------------------------------------------------------
extern "C" void kernel_launch(void* const* d_in, const int* in_sizes, int n_in,
                              void* d_out, int out_size)
{
    const float* x         = (const float*)d_in[0];
    const float* q_weight  = (const float*)d_in[1];
    const float* q_bias    = (const float*)d_in[2];
    const float* k_weight  = (const float*)d_in[3];
    const float* attn_bias = (const float*)d_in[4];

    float* out  = (float*)d_out;                       // [B,S,D]
    float* attn = (float*)d_out + (size_t)B * S * D;   // [B,S,S]

    cudaFuncSetAttribute(logits_mma, cudaFuncAttributeMaxDynamicSharedMemorySize, 147456);
    cudaFuncSetAttribute(out_mma,    cudaFuncAttributeMaxDynamicSharedMemorySize, 221184);

    proj_kernel<<<S, 256>>>(x, q_weight, q_bias, k_weight);

    xsplit_kernel<<<dim3(S / 32, D / 32, B), dim3(32, 8)>>>(x);

    logits_mma<<<128, 256, 147456>>>(attn_bias, attn);

    softmax_kernel<<<B * S, 256>>>(attn);

    out_mma<<<128, 256, 221184>>>(out);
}

// round 7
// speedup vs baseline: 1.1675x; 1.1675x over previous
#include <cuda_runtime.h>
#include <cuda_fp16.h>
#include <mma.h>
#include <cstddef>
#include <cstdint>

using namespace nvcuda;

#define B 16
#define S 1024
#define D 384
#define QK 64

// fp16 operands: A-side split hi/lo (exact), B-side single fp16
__device__ __half g_Qhi[(size_t)B * S * QK];
__device__ __half g_Qlo[(size_t)B * S * QK];
__device__ __half g_Kh [(size_t)B * S * QK];
__device__ __half g_XTh[(size_t)B * D * S];   // [b][c][m]
__device__ __half g_Phi[(size_t)B * S * S];   // softmax probs hi
__device__ __half g_Plo[(size_t)B * S * S];   // softmax probs lo

#define CP_ASYNC16(dst_u32, src_ptr) \
    asm volatile("cp.async.cg.shared.global [%0], [%1], 16;\n" :: "r"(dst_u32), "l"(src_ptr))
#define CP_COMMIT() asm volatile("cp.async.commit_group;\n" ::)
#define CP_WAIT2()  asm volatile("cp.async.wait_group 2;\n" ::)
#define CP_WAIT1()  asm volatile("cp.async.wait_group 1;\n" ::)
#define CP_WAIT0()  asm volatile("cp.async.wait_group 0;\n" ::)

// smem tile: 128 rows x 64 fp16, pitch 72 (144B rows)
#define PITCH 72
#define MAT_BYTES (128 * PITCH * 2)   // 18432

typedef wmma::fragment<wmma::matrix_a, 16, 16, 16, __half, wmma::row_major> FragA;
typedef wmma::fragment<wmma::matrix_b, 16, 16, 16, __half, wmma::col_major> FragB;
typedef wmma::fragment<wmma::accumulator, 16, 16, 16, float> FragC;

// ---------------------------------------------------------------------------
// Kernel 1: per-position Q/K projection -> Q hi/lo fp16, K single fp16
// ---------------------------------------------------------------------------
__global__ __launch_bounds__(256) void proj_kernel(
    const float* __restrict__ x, const float* __restrict__ qw,
    const float* __restrict__ qb, const float* __restrict__ kw)
{
    const int n = blockIdx.x;
    __shared__ float xs[B][D + 1];

    const int tid = threadIdx.x;
    for (int idx = tid; idx < B * D; idx += 256) {
        int b = idx / D, c = idx % D;
        xs[b][c] = x[((size_t)b * S + n) * D + c];
    }
    __syncthreads();

    const int lane = tid & 31;
    const int wid  = tid >> 5;
    const int b    = lane & 15;
    const int half_sel = lane >> 4;
    const float scale = 0.05103103630798287f;  // 384^-0.5

    #pragma unroll
    for (int s = 0; s < 8; s++) {
        const int gidx = (wid * 8 + s) * 2 + half_sel;
        const bool isq = (gidx < 64);
        const int d = isq ? gidx : gidx - 64;
        const float* w = isq ? qw : kw;
        const float4* wp = (const float4*)(w + ((size_t)n * QK + d) * D);

        float a0 = 0.f, a1 = 0.f, a2 = 0.f, a3 = 0.f;
        #pragma unroll 8
        for (int c4 = 0; c4 < D / 4; c4++) {
            float4 wv = __ldg(wp + c4);
            int c = c4 * 4;
            a0 += xs[b][c + 0] * wv.x;
            a1 += xs[b][c + 1] * wv.y;
            a2 += xs[b][c + 2] * wv.z;
            a3 += xs[b][c + 3] * wv.w;
        }
        float acc = (a0 + a1) + (a2 + a3);

        const size_t o = ((size_t)b * S + n) * QK + d;
        if (isq) {
            float qv = scale * (acc + qb[n * QK + d]);
            __half h = __float2half_rn(qv);
            g_Qhi[o] = h;
            g_Qlo[o] = __float2half_rn(qv - __half2float(h));
        } else {
            g_Kh[o] = __float2half_rn(acc);
        }
    }
}

// ---------------------------------------------------------------------------
// Kernel 1b: transpose x -> XT[b][c][m] fp16
// ---------------------------------------------------------------------------
__global__ __launch_bounds__(256) void xsplit_kernel(const float* __restrict__ x)
{
    __shared__ float tb[32][33];
    const int b = blockIdx.z, m0 = blockIdx.x * 32, c0 = blockIdx.y * 32;
    const int tx = threadIdx.x, ty = threadIdx.y;

    #pragma unroll
    for (int j = 0; j < 4; j++)
        tb[ty + 8 * j][tx] = x[((size_t)b * S + m0 + ty + 8 * j) * D + c0 + tx];
    __syncthreads();
    #pragma unroll
    for (int j = 0; j < 4; j++) {
        float v = tb[tx][ty + 8 * j];
        size_t o = ((size_t)b * D + c0 + ty + 8 * j) * S + m0 + tx;
        g_XTh[o] = __float2half_rn(v);
    }
}

// ---------------------------------------------------------------------------
// Kernel 2: logits = Q @ K^T + bias. Grid=128 (b,nt). Qh/Ql resident,
// 8 K-tiles (single matrix each) streamed, 3-buffer pipeline.
// smem = (2 + 3) * 18432 = 92160.
// ---------------------------------------------------------------------------
__global__ __launch_bounds__(256) void logits_mma(
    const float* __restrict__ attn_bias, float* __restrict__ attn)
{
    extern __shared__ __half sm[];
    __half* Qh = sm;
    __half* Ql = sm + 128 * PITCH;

    const int tid = threadIdx.x;
    const int bx = blockIdx.x;
    const int nt = bx & 7, b = bx >> 3;
    const int n0 = nt * 128;

    const uint32_t smb = (uint32_t)__cvta_generic_to_shared(sm);
    const __half* qhp = g_Qhi + ((size_t)b * S + n0) * QK;
    const __half* qlp = g_Qlo + ((size_t)b * S + n0) * QK;
    const __half* khp = g_Kh  + (size_t)b * S * QK;

    #define LOAD_K(mt_, bufj_) do { \
        const uint32_t kb_ = smb + (uint32_t)(2 + (bufj_)) * MAT_BYTES; \
        const __half* kh_ = khp + (size_t)(mt_) * 128 * QK; \
        _Pragma("unroll") \
        for (int i = 0; i < 4; i++) { \
            int g = tid + 256 * i; \
            int r = g >> 3, c16 = g & 7; \
            CP_ASYNC16(kb_ + (uint32_t)(r * 144 + c16 * 16), kh_ + (size_t)r * QK + c16 * 8); \
        } \
    } while (0)

    // prologue: Q hi/lo + K0, K1
    #pragma unroll
    for (int i = 0; i < 4; i++) {
        int g = tid + 256 * i;
        int r = g >> 3, c16 = g & 7;
        CP_ASYNC16(smb + (uint32_t)(r * 144 + c16 * 16), qhp + (size_t)r * QK + c16 * 8);
        CP_ASYNC16(smb + (uint32_t)MAT_BYTES + (uint32_t)(r * 144 + c16 * 16),
                   qlp + (size_t)r * QK + c16 * 8);
    }
    LOAD_K(0, 0); CP_COMMIT();
    LOAD_K(1, 1); CP_COMMIT();

    const int wid = tid >> 5;
    const int wn = wid >> 2;     // 0..1
    const int wm = wid & 3;      // 0..3

    for (int mt = 0; mt < 8; mt++) {
        __syncthreads();
        if (mt + 2 < 8) { LOAD_K(mt + 2, (mt + 2) % 3); CP_COMMIT(); }
        if (mt < 6)       CP_WAIT2();
        else if (mt == 6) CP_WAIT1();
        else              CP_WAIT0();
        __syncthreads();

        const __half* Kh = sm + (size_t)(2 + mt % 3) * 128 * PITCH;
        const int m0 = mt * 128;

        FragC acc[4][2];
        #pragma unroll
        for (int i = 0; i < 4; i++)
            #pragma unroll
            for (int j = 0; j < 2; j++) wmma::fill_fragment(acc[i][j], 0.0f);

        #pragma unroll
        for (int kk = 0; kk < 4; kk++) {
            FragA ah[4], al[4];
            FragB bh[2];
            #pragma unroll
            for (int i = 0; i < 4; i++) {
                int r = wn * 64 + i * 16;
                wmma::load_matrix_sync(ah[i], Qh + r * PITCH + kk * 16, PITCH);
                wmma::load_matrix_sync(al[i], Ql + r * PITCH + kk * 16, PITCH);
            }
            #pragma unroll
            for (int j = 0; j < 2; j++) {
                int c = wm * 32 + j * 16;
                wmma::load_matrix_sync(bh[j], Kh + c * PITCH + kk * 16, PITCH);
            }
            #pragma unroll
            for (int i = 0; i < 4; i++)
                #pragma unroll
                for (int j = 0; j < 2; j++) {
                    wmma::mma_sync(acc[i][j], ah[i], bh[j], acc[i][j]);
                    wmma::mma_sync(acc[i][j], al[i], bh[j], acc[i][j]);
                }
        }

        #pragma unroll
        for (int i = 0; i < 4; i++) {
            const int row = n0 + wn * 64 + i * 16;
            #pragma unroll
            for (int j = 0; j < 2; j++) {
                const int col = m0 + wm * 32 + j * 16;
                FragC bias;
                wmma::load_matrix_sync(bias, attn_bias + (size_t)row * S + col, S,
                                       wmma::mem_row_major);
                #pragma unroll
                for (int e = 0; e < bias.num_elements; e++)
                    acc[i][j].x[e] += bias.x[e];
                wmma::store_matrix_sync(attn + ((size_t)b * S + row) * S + col,
                                        acc[i][j], S, wmma::mem_row_major);
            }
        }
    }
    #undef LOAD_K
}

// ---------------------------------------------------------------------------
// Kernel 3: row softmax; writes fp32 probs + fp16 hi/lo copies
// ---------------------------------------------------------------------------
__global__ __launch_bounds__(256) void softmax_kernel(float* __restrict__ attn)
{
    const size_t rowoff = (size_t)blockIdx.x * S;
    float4* p = (float4*)(attn + rowoff);
    const int tid = threadIdx.x;
    const int lane = tid & 31, w = tid >> 5;

    float4 v = p[tid];
    float m = fmaxf(fmaxf(v.x, v.y), fmaxf(v.z, v.w));
    #pragma unroll
    for (int o = 16; o > 0; o >>= 1) m = fmaxf(m, __shfl_xor_sync(0xffffffffu, m, o));

    __shared__ float redm[8];
    __shared__ float reds[8];
    if (lane == 0) redm[w] = m;
    __syncthreads();
    m = redm[0];
    #pragma unroll
    for (int i = 1; i < 8; i++) m = fmaxf(m, redm[i]);

    float e0 = __expf(v.x - m), e1 = __expf(v.y - m);
    float e2 = __expf(v.z - m), e3 = __expf(v.w - m);
    float ssum = (e0 + e1) + (e2 + e3);
    #pragma unroll
    for (int o = 16; o > 0; o >>= 1) ssum += __shfl_xor_sync(0xffffffffu, ssum, o);
    if (lane == 0) reds[w] = ssum;
    __syncthreads();
    ssum = reds[0];
    #pragma unroll
    for (int i = 1; i < 8; i++) ssum += reds[i];

    const float inv = 1.0f / ssum;
    float v0 = e0 * inv, v1 = e1 * inv, v2 = e2 * inv, v3 = e3 * inv;
    float4 o4 = {v0, v1, v2, v3};
    p[tid] = o4;

    __half h0 = __float2half_rn(v0), h1 = __float2half_rn(v1);
    __half h2 = __float2half_rn(v2), h3 = __float2half_rn(v3);
    __half g0 = __float2half_rn(v0 - __half2float(h0));
    __half g1 = __float2half_rn(v1 - __half2float(h1));
    __half g2 = __float2half_rn(v2 - __half2float(h2));
    __half g3 = __float2half_rn(v3 - __half2float(h3));

    unsigned hi0 = (unsigned)__half_as_ushort(h0) | ((unsigned)__half_as_ushort(h1) << 16);
    unsigned hi1 = (unsigned)__half_as_ushort(h2) | ((unsigned)__half_as_ushort(h3) << 16);
    unsigned lo0 = (unsigned)__half_as_ushort(g0) | ((unsigned)__half_as_ushort(g1) << 16);
    unsigned lo1 = (unsigned)__half_as_ushort(g2) | ((unsigned)__half_as_ushort(g3) << 16);
    *(uint2*)&g_Phi[rowoff + (size_t)tid * 4] = make_uint2(hi0, hi1);
    *(uint2*)&g_Plo[rowoff + (size_t)tid * 4] = make_uint2(lo0, lo1);
}

// ---------------------------------------------------------------------------
// Kernel 4: out = P @ x. Grid=128 (b,nt), 3 ct tiles per block,
// 16 K-chunks of 64, 3-stage pipeline, 3 matrices/chunk (Ph, Pl, XT).
// smem = 3 * 3 * 18432 = 165888.
// ---------------------------------------------------------------------------
__global__ __launch_bounds__(256) void out_mma(float* __restrict__ out)
{
    extern __shared__ __half sm[];

    const int tid = threadIdx.x;
    const int bx = blockIdx.x;
    const int nt = bx & 7, b = bx >> 3;
    const int n0 = nt * 128;

    const uint32_t smb = (uint32_t)__cvta_generic_to_shared(sm);
    const __half* aHp = g_Phi + ((size_t)b * S + n0) * S;
    const __half* aLp = g_Plo + ((size_t)b * S + n0) * S;

    const int wid = tid >> 5;
    const int wn = wid >> 2;
    const int wc = wid & 3;

    for (int ct = 0; ct < 3; ct++) {
        const int c0 = ct * 128;
        const __half* bHp = g_XTh + ((size_t)b * D + c0) * S;
        const __half* srcs[3] = {aHp, aLp, bHp};

        #define LOAD_CHUNK(kc_, bufj_) do { \
            const int kof_ = (kc_) * 64; \
            const uint32_t bb_ = smb + (uint32_t)(bufj_) * (3u * MAT_BYTES); \
            _Pragma("unroll") \
            for (int mtx = 0; mtx < 3; mtx++) { \
                const __half* src = srcs[mtx] + kof_; \
                const uint32_t dst = bb_ + (uint32_t)mtx * MAT_BYTES; \
                _Pragma("unroll") \
                for (int i = 0; i < 4; i++) { \
                    int g = tid + 256 * i; \
                    int r = g >> 3, c16 = g & 7; \
                    CP_ASYNC16(dst + (uint32_t)(r * 144 + c16 * 16), \
                               src + (size_t)r * S + c16 * 8); \
                } \
            } \
        } while (0)

        __syncthreads();
        LOAD_CHUNK(0, 0); CP_COMMIT();
        LOAD_CHUNK(1, 1); CP_COMMIT();

        FragC acc[4][2];
        #pragma unroll
        for (int i = 0; i < 4; i++)
            #pragma unroll
            for (int j = 0; j < 2; j++) wmma::fill_fragment(acc[i][j], 0.0f);

        for (int kc = 0; kc < 16; kc++) {
            __syncthreads();
            if (kc + 2 < 16) { LOAD_CHUNK(kc + 2, (kc + 2) % 3); CP_COMMIT(); }
            if (kc < 14)       CP_WAIT2();
            else if (kc == 14) CP_WAIT1();
            else               CP_WAIT0();
            __syncthreads();

            const __half* base = sm + (size_t)(kc % 3) * (3 * 128 * PITCH);
            const __half* Ah = base;
            const __half* Al = base + 128 * PITCH;
            const __half* Bh = base + 2 * 128 * PITCH;

            #pragma unroll
            for (int kk = 0; kk < 4; kk++) {
                FragA ah[4], al[4];
                FragB bh[2];
                #pragma unroll
                for (int i = 0; i < 4; i++) {
                    int r = wn * 64 + i * 16;
                    wmma::load_matrix_sync(ah[i], Ah + r * PITCH + kk * 16, PITCH);
                    wmma::load_matrix_sync(al[i], Al + r * PITCH + kk * 16, PITCH);
                }
                #pragma unroll
                for (int j = 0; j < 2; j++) {
                    int c = wc * 32 + j * 16;
                    wmma::load_matrix_sync(bh[j], Bh + c * PITCH + kk * 16, PITCH);
                }
                #pragma unroll
                for (int i = 0; i < 4; i++)
                    #pragma unroll
                    for (int j = 0; j < 2; j++) {
                        wmma::mma_sync(acc[i][j], ah[i], bh[j], acc[i][j]);
                        wmma::mma_sync(acc[i][j], al[i], bh[j], acc[i][j]);
                    }
            }
        }

        #pragma unroll
        for (int i = 0; i < 4; i++) {
            const int row = n0 + wn * 64 + i * 16;
            #pragma unroll
            for (int j = 0; j < 2; j++) {
                const int col = c0 + wc * 32 + j * 16;
                wmma::store_matrix_sync(out + ((size_t)b * S + row) * D + col,
                                        acc[i][j], D, wmma::mem_row_major);
            }
        }
        #undef LOAD_CHUNK
    }
}

// ---------------------------------------------------------------------------
extern "C" void kernel_launch(void* const* d_in, const int* in_sizes, int n_in,
                              void* d_out, int out_size)
{
    const float* x         = (const float*)d_in[0];
    const float* q_weight  = (const float*)d_in[1];
    const float* q_bias    = (const float*)d_in[2];
    const float* k_weight  = (const float*)d_in[3];
    const float* attn_bias = (const float*)d_in[4];

    float* out  = (float*)d_out;                       // [B,S,D]
    float* attn = (float*)d_out + (size_t)B * S * D;   // [B,S,S]

    cudaFuncSetAttribute(logits_mma, cudaFuncAttributeMaxDynamicSharedMemorySize, 92160);
    cudaFuncSetAttribute(out_mma,    cudaFuncAttributeMaxDynamicSharedMemorySize, 165888);

    proj_kernel<<<S, 256>>>(x, q_weight, q_bias, k_weight);

    xsplit_kernel<<<dim3(S / 32, D / 32, B), dim3(32, 8)>>>(x);

    logits_mma<<<128, 256, 92160>>>(attn_bias, attn);

    softmax_kernel<<<B * S, 256>>>(attn);

    out_mma<<<128, 256, 165888>>>(out);
}

// round 8
// speedup vs baseline: 1.3019x; 1.1151x over previous
#include <cuda_runtime.h>
#include <cuda_fp16.h>
#include <mma.h>
#include <cstddef>
#include <cstdint>

using namespace nvcuda;

#define B 16
#define S 1024
#define D 384
#define QK 64

// fp16 operands: Q split hi/lo (exact), K / X / P single fp16
__device__ __half g_Qhi[(size_t)B * S * QK];
__device__ __half g_Qlo[(size_t)B * S * QK];
__device__ __half g_Kh [(size_t)B * S * QK];
__device__ __half g_XTh[(size_t)B * D * S];   // [b][c][m]
__device__ __half g_Ph [(size_t)B * S * S];   // softmax probs fp16

#define CP_ASYNC16(dst_u32, src_ptr) \
    asm volatile("cp.async.cg.shared.global [%0], [%1], 16;\n" :: "r"(dst_u32), "l"(src_ptr))
#define CP_COMMIT() asm volatile("cp.async.commit_group;\n" ::)
#define CP_WAIT2()  asm volatile("cp.async.wait_group 2;\n" ::)
#define CP_WAIT1()  asm volatile("cp.async.wait_group 1;\n" ::)
#define CP_WAIT0()  asm volatile("cp.async.wait_group 0;\n" ::)

// smem tile: 128 rows x 64 fp16, pitch 72 (144B rows)
#define PITCH 72
#define MAT_BYTES (128 * PITCH * 2)   // 18432

typedef wmma::fragment<wmma::matrix_a, 16, 16, 16, __half, wmma::row_major> FragA;
typedef wmma::fragment<wmma::matrix_b, 16, 16, 16, __half, wmma::col_major> FragB;
typedef wmma::fragment<wmma::accumulator, 16, 16, 16, float> FragC;

// ---------------------------------------------------------------------------
// Kernel 1: per-position Q/K projection -> Q hi/lo fp16, K single fp16
// ---------------------------------------------------------------------------
__global__ __launch_bounds__(256) void proj_kernel(
    const float* __restrict__ x, const float* __restrict__ qw,
    const float* __restrict__ qb, const float* __restrict__ kw)
{
    const int n = blockIdx.x;
    __shared__ float xs[B][D + 1];

    const int tid = threadIdx.x;
    for (int idx = tid; idx < B * D; idx += 256) {
        int b = idx / D, c = idx % D;
        xs[b][c] = x[((size_t)b * S + n) * D + c];
    }
    __syncthreads();

    const int lane = tid & 31;
    const int wid  = tid >> 5;
    const int b    = lane & 15;
    const int half_sel = lane >> 4;
    const float scale = 0.05103103630798287f;  // 384^-0.5

    #pragma unroll
    for (int s = 0; s < 8; s++) {
        const int gidx = (wid * 8 + s) * 2 + half_sel;
        const bool isq = (gidx < 64);
        const int d = isq ? gidx : gidx - 64;
        const float* w = isq ? qw : kw;
        const float4* wp = (const float4*)(w + ((size_t)n * QK + d) * D);

        float a0 = 0.f, a1 = 0.f, a2 = 0.f, a3 = 0.f;
        #pragma unroll 8
        for (int c4 = 0; c4 < D / 4; c4++) {
            float4 wv = __ldg(wp + c4);
            int c = c4 * 4;
            a0 += xs[b][c + 0] * wv.x;
            a1 += xs[b][c + 1] * wv.y;
            a2 += xs[b][c + 2] * wv.z;
            a3 += xs[b][c + 3] * wv.w;
        }
        float acc = (a0 + a1) + (a2 + a3);

        const size_t o = ((size_t)b * S + n) * QK + d;
        if (isq) {
            float qv = scale * (acc + qb[n * QK + d]);
            __half h = __float2half_rn(qv);
            g_Qhi[o] = h;
            g_Qlo[o] = __float2half_rn(qv - __half2float(h));
        } else {
            g_Kh[o] = __float2half_rn(acc);
        }
    }
}

// ---------------------------------------------------------------------------
// Kernel 1b: transpose x -> XT[b][c][m] fp16
// ---------------------------------------------------------------------------
__global__ __launch_bounds__(256) void xsplit_kernel(const float* __restrict__ x)
{
    __shared__ float tb[32][33];
    const int b = blockIdx.z, m0 = blockIdx.x * 32, c0 = blockIdx.y * 32;
    const int tx = threadIdx.x, ty = threadIdx.y;

    #pragma unroll
    for (int j = 0; j < 4; j++)
        tb[ty + 8 * j][tx] = x[((size_t)b * S + m0 + ty + 8 * j) * D + c0 + tx];
    __syncthreads();
    #pragma unroll
    for (int j = 0; j < 4; j++) {
        float v = tb[tx][ty + 8 * j];
        size_t o = ((size_t)b * D + c0 + ty + 8 * j) * S + m0 + tx;
        g_XTh[o] = __float2half_rn(v);
    }
}

// ---------------------------------------------------------------------------
// Kernel 2: logits = Q @ K^T + bias. Grid=128 (b,nt). Qh/Ql resident,
// 8 K-tiles streamed, 3-buffer pipeline. smem = 5 * 18432 = 92160.
// ---------------------------------------------------------------------------
__global__ __launch_bounds__(256) void logits_mma(
    const float* __restrict__ attn_bias, float* __restrict__ attn)
{
    extern __shared__ __half sm[];
    __half* Qh = sm;
    __half* Ql = sm + 128 * PITCH;

    const int tid = threadIdx.x;
    const int bx = blockIdx.x;
    const int nt = bx & 7, b = bx >> 3;
    const int n0 = nt * 128;

    const uint32_t smb = (uint32_t)__cvta_generic_to_shared(sm);
    const __half* qhp = g_Qhi + ((size_t)b * S + n0) * QK;
    const __half* qlp = g_Qlo + ((size_t)b * S + n0) * QK;
    const __half* khp = g_Kh  + (size_t)b * S * QK;

    #define LOAD_K(mt_, bufj_) do { \
        const uint32_t kb_ = smb + (uint32_t)(2 + (bufj_)) * MAT_BYTES; \
        const __half* kh_ = khp + (size_t)(mt_) * 128 * QK; \
        _Pragma("unroll") \
        for (int i = 0; i < 4; i++) { \
            int g = tid + 256 * i; \
            int r = g >> 3, c16 = g & 7; \
            CP_ASYNC16(kb_ + (uint32_t)(r * 144 + c16 * 16), kh_ + (size_t)r * QK + c16 * 8); \
        } \
    } while (0)

    #pragma unroll
    for (int i = 0; i < 4; i++) {
        int g = tid + 256 * i;
        int r = g >> 3, c16 = g & 7;
        CP_ASYNC16(smb + (uint32_t)(r * 144 + c16 * 16), qhp + (size_t)r * QK + c16 * 8);
        CP_ASYNC16(smb + (uint32_t)MAT_BYTES + (uint32_t)(r * 144 + c16 * 16),
                   qlp + (size_t)r * QK + c16 * 8);
    }
    LOAD_K(0, 0); CP_COMMIT();
    LOAD_K(1, 1); CP_COMMIT();

    const int wid = tid >> 5;
    const int wn = wid >> 2;     // 0..1
    const int wm = wid & 3;      // 0..3

    for (int mt = 0; mt < 8; mt++) {
        __syncthreads();
        if (mt + 2 < 8) { LOAD_K(mt + 2, (mt + 2) % 3); CP_COMMIT(); }
        if (mt < 6)       CP_WAIT2();
        else if (mt == 6) CP_WAIT1();
        else              CP_WAIT0();
        __syncthreads();

        const __half* Kh = sm + (size_t)(2 + mt % 3) * 128 * PITCH;
        const int m0 = mt * 128;

        FragC acc[4][2];
        #pragma unroll
        for (int i = 0; i < 4; i++)
            #pragma unroll
            for (int j = 0; j < 2; j++) wmma::fill_fragment(acc[i][j], 0.0f);

        #pragma unroll
        for (int kk = 0; kk < 4; kk++) {
            FragA ah[4], al[4];
            FragB bh[2];
            #pragma unroll
            for (int i = 0; i < 4; i++) {
                int r = wn * 64 + i * 16;
                wmma::load_matrix_sync(ah[i], Qh + r * PITCH + kk * 16, PITCH);
                wmma::load_matrix_sync(al[i], Ql + r * PITCH + kk * 16, PITCH);
            }
            #pragma unroll
            for (int j = 0; j < 2; j++) {
                int c = wm * 32 + j * 16;
                wmma::load_matrix_sync(bh[j], Kh + c * PITCH + kk * 16, PITCH);
            }
            #pragma unroll
            for (int i = 0; i < 4; i++)
                #pragma unroll
                for (int j = 0; j < 2; j++) {
                    wmma::mma_sync(acc[i][j], ah[i], bh[j], acc[i][j]);
                    wmma::mma_sync(acc[i][j], al[i], bh[j], acc[i][j]);
                }
        }

        #pragma unroll
        for (int i = 0; i < 4; i++) {
            const int row = n0 + wn * 64 + i * 16;
            #pragma unroll
            for (int j = 0; j < 2; j++) {
                const int col = m0 + wm * 32 + j * 16;
                FragC bias;
                wmma::load_matrix_sync(bias, attn_bias + (size_t)row * S + col, S,
                                       wmma::mem_row_major);
                #pragma unroll
                for (int e = 0; e < bias.num_elements; e++)
                    acc[i][j].x[e] += bias.x[e];
                wmma::store_matrix_sync(attn + ((size_t)b * S + row) * S + col,
                                        acc[i][j], S, wmma::mem_row_major);
            }
        }
    }
    #undef LOAD_K
}

// ---------------------------------------------------------------------------
// Kernel 3: row softmax; writes fp32 probs + single fp16 copy
// ---------------------------------------------------------------------------
__global__ __launch_bounds__(256) void softmax_kernel(float* __restrict__ attn)
{
    const size_t rowoff = (size_t)blockIdx.x * S;
    float4* p = (float4*)(attn + rowoff);
    const int tid = threadIdx.x;
    const int lane = tid & 31, w = tid >> 5;

    float4 v = p[tid];
    float m = fmaxf(fmaxf(v.x, v.y), fmaxf(v.z, v.w));
    #pragma unroll
    for (int o = 16; o > 0; o >>= 1) m = fmaxf(m, __shfl_xor_sync(0xffffffffu, m, o));

    __shared__ float redm[8];
    __shared__ float reds[8];
    if (lane == 0) redm[w] = m;
    __syncthreads();
    m = redm[0];
    #pragma unroll
    for (int i = 1; i < 8; i++) m = fmaxf(m, redm[i]);

    float e0 = __expf(v.x - m), e1 = __expf(v.y - m);
    float e2 = __expf(v.z - m), e3 = __expf(v.w - m);
    float ssum = (e0 + e1) + (e2 + e3);
    #pragma unroll
    for (int o = 16; o > 0; o >>= 1) ssum += __shfl_xor_sync(0xffffffffu, ssum, o);
    if (lane == 0) reds[w] = ssum;
    __syncthreads();
    ssum = reds[0];
    #pragma unroll
    for (int i = 1; i < 8; i++) ssum += reds[i];

    const float inv = 1.0f / ssum;
    float v0 = e0 * inv, v1 = e1 * inv, v2 = e2 * inv, v3 = e3 * inv;
    float4 o4 = {v0, v1, v2, v3};
    p[tid] = o4;

    __half h0 = __float2half_rn(v0), h1 = __float2half_rn(v1);
    __half h2 = __float2half_rn(v2), h3 = __float2half_rn(v3);
    unsigned hi0 = (unsigned)__half_as_ushort(h0) | ((unsigned)__half_as_ushort(h1) << 16);
    unsigned hi1 = (unsigned)__half_as_ushort(h2) | ((unsigned)__half_as_ushort(h3) << 16);
    *(uint2*)&g_Ph[rowoff + (size_t)tid * 4] = make_uint2(hi0, hi1);
}

// ---------------------------------------------------------------------------
// Kernel 4: out = P @ x. Grid=128 (b,nt), 3 ct tiles per block,
// 16 K-chunks of 64, 3-stage pipeline, 2 matrices/chunk (P, XT).
// smem = 3 * 2 * 18432 = 110592.
// ---------------------------------------------------------------------------
__global__ __launch_bounds__(256) void out_mma(float* __restrict__ out)
{
    extern __shared__ __half sm[];

    const int tid = threadIdx.x;
    const int bx = blockIdx.x;
    const int nt = bx & 7, b = bx >> 3;
    const int n0 = nt * 128;

    const uint32_t smb = (uint32_t)__cvta_generic_to_shared(sm);
    const __half* aHp = g_Ph + ((size_t)b * S + n0) * S;

    const int wid = tid >> 5;
    const int wn = wid >> 2;
    const int wc = wid & 3;

    for (int ct = 0; ct < 3; ct++) {
        const int c0 = ct * 128;
        const __half* bHp = g_XTh + ((size_t)b * D + c0) * S;
        const __half* srcs[2] = {aHp, bHp};

        #define LOAD_CHUNK(kc_, bufj_) do { \
            const int kof_ = (kc_) * 64; \
            const uint32_t bb_ = smb + (uint32_t)(bufj_) * (2u * MAT_BYTES); \
            _Pragma("unroll") \
            for (int mtx = 0; mtx < 2; mtx++) { \
                const __half* src = srcs[mtx] + kof_; \
                const uint32_t dst = bb_ + (uint32_t)mtx * MAT_BYTES; \
                _Pragma("unroll") \
                for (int i = 0; i < 4; i++) { \
                    int g = tid + 256 * i; \
                    int r = g >> 3, c16 = g & 7; \
                    CP_ASYNC16(dst + (uint32_t)(r * 144 + c16 * 16), \
                               src + (size_t)r * S + c16 * 8); \
                } \
            } \
        } while (0)

        __syncthreads();
        LOAD_CHUNK(0, 0); CP_COMMIT();
        LOAD_CHUNK(1, 1); CP_COMMIT();

        FragC acc[4][2];
        #pragma unroll
        for (int i = 0; i < 4; i++)
            #pragma unroll
            for (int j = 0; j < 2; j++) wmma::fill_fragment(acc[i][j], 0.0f);

        for (int kc = 0; kc < 16; kc++) {
            __syncthreads();
            if (kc + 2 < 16) { LOAD_CHUNK(kc + 2, (kc + 2) % 3); CP_COMMIT(); }
            if (kc < 14)       CP_WAIT2();
            else if (kc == 14) CP_WAIT1();
            else               CP_WAIT0();
            __syncthreads();

            const __half* base = sm + (size_t)(kc % 3) * (2 * 128 * PITCH);
            const __half* Ah = base;
            const __half* Bh = base + 128 * PITCH;

            #pragma unroll
            for (int kk = 0; kk < 4; kk++) {
                FragA ah[4];
                FragB bh[2];
                #pragma unroll
                for (int i = 0; i < 4; i++) {
                    int r = wn * 64 + i * 16;
                    wmma::load_matrix_sync(ah[i], Ah + r * PITCH + kk * 16, PITCH);
                }
                #pragma unroll
                for (int j = 0; j < 2; j++) {
                    int c = wc * 32 + j * 16;
                    wmma::load_matrix_sync(bh[j], Bh + c * PITCH + kk * 16, PITCH);
                }
                #pragma unroll
                for (int i = 0; i < 4; i++)
                    #pragma unroll
                    for (int j = 0; j < 2; j++)
                        wmma::mma_sync(acc[i][j], ah[i], bh[j], acc[i][j]);
            }
        }

        #pragma unroll
        for (int i = 0; i < 4; i++) {
            const int row = n0 + wn * 64 + i * 16;
            #pragma unroll
            for (int j = 0; j < 2; j++) {
                const int col = c0 + wc * 32 + j * 16;
                wmma::store_matrix_sync(out + ((size_t)b * S + row) * D + col,
                                        acc[i][j], D, wmma::mem_row_major);
            }
        }
        #undef LOAD_CHUNK
    }
}

// ---------------------------------------------------------------------------
extern "C" void kernel_launch(void* const* d_in, const int* in_sizes, int n_in,
                              void* d_out, int out_size)
{
    const float* x         = (const float*)d_in[0];
    const float* q_weight  = (const float*)d_in[1];
    const float* q_bias    = (const float*)d_in[2];
    const float* k_weight  = (const float*)d_in[3];
    const float* attn_bias = (const float*)d_in[4];

    float* out  = (float*)d_out;                       // [B,S,D]
    float* attn = (float*)d_out + (size_t)B * S * D;   // [B,S,S]

    cudaFuncSetAttribute(logits_mma, cudaFuncAttributeMaxDynamicSharedMemorySize, 92160);
    cudaFuncSetAttribute(out_mma,    cudaFuncAttributeMaxDynamicSharedMemorySize, 110592);

    proj_kernel<<<S, 256>>>(x, q_weight, q_bias, k_weight);

    xsplit_kernel<<<dim3(S / 32, D / 32, B), dim3(32, 8)>>>(x);

    logits_mma<<<128, 256, 92160>>>(attn_bias, attn);

    softmax_kernel<<<B * S, 256>>>(attn);

    out_mma<<<128, 256, 110592>>>(out);
}

// round 9
// speedup vs baseline: 1.3665x; 1.0496x over previous
#include <cuda_runtime.h>
#include <cuda_fp16.h>
#include <mma.h>
#include <cstddef>
#include <cstdint>

using namespace nvcuda;

#define B 16
#define S 1024
#define D 384
#define QK 64

// fp16 operands (single precision level everywhere; error budget verified)
__device__ __half g_Qh [(size_t)B * S * QK];
__device__ __half g_Kh [(size_t)B * S * QK];
__device__ __half g_XTh[(size_t)B * D * S];   // [b][c][m]
__device__ __half g_Ph [(size_t)B * S * S];   // softmax probs fp16

#define CP_ASYNC16(dst_u32, src_ptr) \
    asm volatile("cp.async.cg.shared.global [%0], [%1], 16;\n" :: "r"(dst_u32), "l"(src_ptr))
#define CP_COMMIT() asm volatile("cp.async.commit_group;\n" ::)
#define CP_WAIT2()  asm volatile("cp.async.wait_group 2;\n" ::)
#define CP_WAIT1()  asm volatile("cp.async.wait_group 1;\n" ::)
#define CP_WAIT0()  asm volatile("cp.async.wait_group 0;\n" ::)

// smem tile: 128 rows x 64 fp16, pitch 72 (144B rows)
#define PITCH 72
#define MAT_BYTES (128 * PITCH * 2)   // 18432
#define SPITCH 132                    // fp32 staging pitch (floats)

typedef wmma::fragment<wmma::matrix_a, 16, 16, 16, __half, wmma::row_major> FragA;
typedef wmma::fragment<wmma::matrix_b, 16, 16, 16, __half, wmma::col_major> FragB;
typedef wmma::fragment<wmma::accumulator, 16, 16, 16, float> FragC;

// ---------------------------------------------------------------------------
// Kernel 1: per-position Q/K projection -> single fp16
// ---------------------------------------------------------------------------
__global__ __launch_bounds__(256) void proj_kernel(
    const float* __restrict__ x, const float* __restrict__ qw,
    const float* __restrict__ qb, const float* __restrict__ kw)
{
    const int n = blockIdx.x;
    __shared__ float xs[B][D + 1];

    const int tid = threadIdx.x;
    for (int idx = tid; idx < B * D; idx += 256) {
        int b = idx / D, c = idx % D;
        xs[b][c] = x[((size_t)b * S + n) * D + c];
    }
    __syncthreads();

    const int lane = tid & 31;
    const int wid  = tid >> 5;
    const int b    = lane & 15;
    const int half_sel = lane >> 4;
    const float scale = 0.05103103630798287f;  // 384^-0.5

    #pragma unroll
    for (int s = 0; s < 8; s++) {
        const int gidx = (wid * 8 + s) * 2 + half_sel;
        const bool isq = (gidx < 64);
        const int d = isq ? gidx : gidx - 64;
        const float* w = isq ? qw : kw;
        const float4* wp = (const float4*)(w + ((size_t)n * QK + d) * D);

        float a0 = 0.f, a1 = 0.f, a2 = 0.f, a3 = 0.f;
        #pragma unroll 8
        for (int c4 = 0; c4 < D / 4; c4++) {
            float4 wv = __ldg(wp + c4);
            int c = c4 * 4;
            a0 += xs[b][c + 0] * wv.x;
            a1 += xs[b][c + 1] * wv.y;
            a2 += xs[b][c + 2] * wv.z;
            a3 += xs[b][c + 3] * wv.w;
        }
        float acc = (a0 + a1) + (a2 + a3);

        const size_t o = ((size_t)b * S + n) * QK + d;
        if (isq) g_Qh[o] = __float2half_rn(scale * (acc + qb[n * QK + d]));
        else     g_Kh[o] = __float2half_rn(acc);
    }
}

// ---------------------------------------------------------------------------
// Kernel 1b: transpose x -> XT[b][c][m] fp16
// ---------------------------------------------------------------------------
__global__ __launch_bounds__(256) void xsplit_kernel(const float* __restrict__ x)
{
    __shared__ float tb[32][33];
    const int b = blockIdx.z, m0 = blockIdx.x * 32, c0 = blockIdx.y * 32;
    const int tx = threadIdx.x, ty = threadIdx.y;

    #pragma unroll
    for (int j = 0; j < 4; j++)
        tb[ty + 8 * j][tx] = x[((size_t)b * S + m0 + ty + 8 * j) * D + c0 + tx];
    __syncthreads();
    #pragma unroll
    for (int j = 0; j < 4; j++) {
        float v = tb[tx][ty + 8 * j];
        size_t o = ((size_t)b * D + c0 + ty + 8 * j) * S + m0 + tx;
        g_XTh[o] = __float2half_rn(v);
    }
}

// ---------------------------------------------------------------------------
// Kernel 2: logits = Q @ K^T + bias, FUSED row softmax.
// Grid=128 (b,nt): block owns 128 complete rows. Q resident, 8 K-tiles
// streamed (3-buffer). Epilogue per tile: acc -> smem stage -> coalesced
// bias-add + attn store. After all tiles: in-kernel softmax over own rows
// (L2-hot re-read), overwrite attn fp32 + write P fp16.
// smem = 4*18432 (Q + 3 K bufs) + 128*132*4 (stage) = 141312.
// ---------------------------------------------------------------------------
__global__ __launch_bounds__(256) void logits_mma(
    const float* __restrict__ attn_bias, float* __restrict__ attn)
{
    extern __shared__ __half sm[];
    __half* Qh = sm;
    float* stage = (float*)(sm + 4 * 128 * PITCH);

    const int tid = threadIdx.x;
    const int bx = blockIdx.x;
    const int nt = bx & 7, b = bx >> 3;
    const int n0 = nt * 128;

    const uint32_t smb = (uint32_t)__cvta_generic_to_shared(sm);
    const __half* qhp = g_Qh + ((size_t)b * S + n0) * QK;
    const __half* khp = g_Kh + (size_t)b * S * QK;

    #define LOAD_K(mt_, bufj_) do { \
        const uint32_t kb_ = smb + (uint32_t)(1 + (bufj_)) * MAT_BYTES; \
        const __half* kh_ = khp + (size_t)(mt_) * 128 * QK; \
        _Pragma("unroll") \
        for (int i = 0; i < 4; i++) { \
            int g = tid + 256 * i; \
            int r = g >> 3, c16 = g & 7; \
            CP_ASYNC16(kb_ + (uint32_t)(r * 144 + c16 * 16), kh_ + (size_t)r * QK + c16 * 8); \
        } \
    } while (0)

    // prologue: Q + K0, K1
    #pragma unroll
    for (int i = 0; i < 4; i++) {
        int g = tid + 256 * i;
        int r = g >> 3, c16 = g & 7;
        CP_ASYNC16(smb + (uint32_t)(r * 144 + c16 * 16), qhp + (size_t)r * QK + c16 * 8);
    }
    LOAD_K(0, 0); CP_COMMIT();
    LOAD_K(1, 1); CP_COMMIT();

    const int wid = tid >> 5;
    const int lane = tid & 31;
    const int wn = wid >> 2;     // 0..1
    const int wm = wid & 3;      // 0..3

    for (int mt = 0; mt < 8; mt++) {
        __syncthreads();                 // stage + K buffer reuse barrier
        if (mt + 2 < 8) { LOAD_K(mt + 2, (mt + 2) % 3); CP_COMMIT(); }
        if (mt < 6)       CP_WAIT2();
        else if (mt == 6) CP_WAIT1();
        else              CP_WAIT0();
        __syncthreads();

        const __half* Kh = sm + (size_t)(1 + mt % 3) * 128 * PITCH;
        const int m0 = mt * 128;

        FragC acc[4][2];
        #pragma unroll
        for (int i = 0; i < 4; i++)
            #pragma unroll
            for (int j = 0; j < 2; j++) wmma::fill_fragment(acc[i][j], 0.0f);

        #pragma unroll
        for (int kk = 0; kk < 4; kk++) {
            FragA ah[4];
            FragB bh[2];
            #pragma unroll
            for (int i = 0; i < 4; i++) {
                int r = wn * 64 + i * 16;
                wmma::load_matrix_sync(ah[i], Qh + r * PITCH + kk * 16, PITCH);
            }
            #pragma unroll
            for (int j = 0; j < 2; j++) {
                int c = wm * 32 + j * 16;
                wmma::load_matrix_sync(bh[j], Kh + c * PITCH + kk * 16, PITCH);
            }
            #pragma unroll
            for (int i = 0; i < 4; i++)
                #pragma unroll
                for (int j = 0; j < 2; j++)
                    wmma::mma_sync(acc[i][j], ah[i], bh[j], acc[i][j]);
        }

        // stage accumulators in smem (scattered, but smem is cheap)
        #pragma unroll
        for (int i = 0; i < 4; i++)
            #pragma unroll
            for (int j = 0; j < 2; j++)
                wmma::store_matrix_sync(
                    stage + (size_t)(wn * 64 + i * 16) * SPITCH + wm * 32 + j * 16,
                    acc[i][j], SPITCH, wmma::mem_row_major);
        __syncthreads();

        // coalesced bias add + raw-logit store: 128 rows x 32 float4
        #pragma unroll
        for (int i = 0; i < 16; i++) {
            int g = tid + 256 * i;
            int r = g >> 5, c4 = (g & 31) * 4;
            float4 v = *(float4*)&stage[(size_t)r * SPITCH + c4];
            float4 bb = __ldg((const float4*)&attn_bias[(size_t)(n0 + r) * S + m0 + c4]);
            v.x += bb.x; v.y += bb.y; v.z += bb.z; v.w += bb.w;
            *(float4*)&attn[((size_t)b * S + n0 + r) * S + m0 + c4] = v;
        }
    }

    // ---- fused softmax over this block's 128 complete rows ----
    __syncthreads();
    #pragma unroll 1
    for (int rr = 0; rr < 16; rr++) {
        const int r = wid * 16 + rr;
        float* rowp = attn + ((size_t)b * S + n0 + r) * S;
        __half* php = g_Ph + ((size_t)b * S + n0 + r) * S;

        float4 v[8];
        #pragma unroll
        for (int j = 0; j < 8; j++)
            v[j] = *(float4*)&rowp[j * 128 + lane * 4];

        float mx = -1e30f;
        #pragma unroll
        for (int j = 0; j < 8; j++)
            mx = fmaxf(mx, fmaxf(fmaxf(v[j].x, v[j].y), fmaxf(v[j].z, v[j].w)));
        #pragma unroll
        for (int o = 16; o > 0; o >>= 1) mx = fmaxf(mx, __shfl_xor_sync(0xffffffffu, mx, o));

        float ssum = 0.f;
        #pragma unroll
        for (int j = 0; j < 8; j++) {
            v[j].x = __expf(v[j].x - mx); v[j].y = __expf(v[j].y - mx);
            v[j].z = __expf(v[j].z - mx); v[j].w = __expf(v[j].w - mx);
            ssum += (v[j].x + v[j].y) + (v[j].z + v[j].w);
        }
        #pragma unroll
        for (int o = 16; o > 0; o >>= 1) ssum += __shfl_xor_sync(0xffffffffu, ssum, o);
        const float inv = 1.0f / ssum;

        #pragma unroll
        for (int j = 0; j < 8; j++) {
            float p0 = v[j].x * inv, p1 = v[j].y * inv;
            float p2 = v[j].z * inv, p3 = v[j].w * inv;
            float4 o4 = {p0, p1, p2, p3};
            *(float4*)&rowp[j * 128 + lane * 4] = o4;
            __half h0 = __float2half_rn(p0), h1 = __float2half_rn(p1);
            __half h2 = __float2half_rn(p2), h3 = __float2half_rn(p3);
            unsigned u0 = (unsigned)__half_as_ushort(h0) | ((unsigned)__half_as_ushort(h1) << 16);
            unsigned u1 = (unsigned)__half_as_ushort(h2) | ((unsigned)__half_as_ushort(h3) << 16);
            *(uint2*)&php[j * 128 + lane * 4] = make_uint2(u0, u1);
        }
    }
    #undef LOAD_K
}

// ---------------------------------------------------------------------------
// Kernel 4: out = P @ x. Grid=128 (b,nt), 3 ct tiles per block,
// 16 K-chunks of 64, 3-stage pipeline, 2 matrices/chunk (P, XT).
// smem = 3 * 2 * 18432 = 110592.
// ---------------------------------------------------------------------------
__global__ __launch_bounds__(256) void out_mma(float* __restrict__ out)
{
    extern __shared__ __half sm[];

    const int tid = threadIdx.x;
    const int bx = blockIdx.x;
    const int nt = bx & 7, b = bx >> 3;
    const int n0 = nt * 128;

    const uint32_t smb = (uint32_t)__cvta_generic_to_shared(sm);
    const __half* aHp = g_Ph + ((size_t)b * S + n0) * S;

    const int wid = tid >> 5;
    const int wn = wid >> 2;
    const int wc = wid & 3;

    for (int ct = 0; ct < 3; ct++) {
        const int c0 = ct * 128;
        const __half* bHp = g_XTh + ((size_t)b * D + c0) * S;
        const __half* srcs[2] = {aHp, bHp};

        #define LOAD_CHUNK(kc_, bufj_) do { \
            const int kof_ = (kc_) * 64; \
            const uint32_t bb_ = smb + (uint32_t)(bufj_) * (2u * MAT_BYTES); \
            _Pragma("unroll") \
            for (int mtx = 0; mtx < 2; mtx++) { \
                const __half* src = srcs[mtx] + kof_; \
                const uint32_t dst = bb_ + (uint32_t)mtx * MAT_BYTES; \
                _Pragma("unroll") \
                for (int i = 0; i < 4; i++) { \
                    int g = tid + 256 * i; \
                    int r = g >> 3, c16 = g & 7; \
                    CP_ASYNC16(dst + (uint32_t)(r * 144 + c16 * 16), \
                               src + (size_t)r * S + c16 * 8); \
                } \
            } \
        } while (0)

        __syncthreads();
        LOAD_CHUNK(0, 0); CP_COMMIT();
        LOAD_CHUNK(1, 1); CP_COMMIT();

        FragC acc[4][2];
        #pragma unroll
        for (int i = 0; i < 4; i++)
            #pragma unroll
            for (int j = 0; j < 2; j++) wmma::fill_fragment(acc[i][j], 0.0f);

        for (int kc = 0; kc < 16; kc++) {
            __syncthreads();
            if (kc + 2 < 16) { LOAD_CHUNK(kc + 2, (kc + 2) % 3); CP_COMMIT(); }
            if (kc < 14)       CP_WAIT2();
            else if (kc == 14) CP_WAIT1();
            else               CP_WAIT0();
            __syncthreads();

            const __half* base = sm + (size_t)(kc % 3) * (2 * 128 * PITCH);
            const __half* Ah = base;
            const __half* Bh = base + 128 * PITCH;

            #pragma unroll
            for (int kk = 0; kk < 4; kk++) {
                FragA ah[4];
                FragB bh[2];
                #pragma unroll
                for (int i = 0; i < 4; i++) {
                    int r = wn * 64 + i * 16;
                    wmma::load_matrix_sync(ah[i], Ah + r * PITCH + kk * 16, PITCH);
                }
                #pragma unroll
                for (int j = 0; j < 2; j++) {
                    int c = wc * 32 + j * 16;
                    wmma::load_matrix_sync(bh[j], Bh + c * PITCH + kk * 16, PITCH);
                }
                #pragma unroll
                for (int i = 0; i < 4; i++)
                    #pragma unroll
                    for (int j = 0; j < 2; j++)
                        wmma::mma_sync(acc[i][j], ah[i], bh[j], acc[i][j]);
            }
        }

        #pragma unroll
        for (int i = 0; i < 4; i++) {
            const int row = n0 + wn * 64 + i * 16;
            #pragma unroll
            for (int j = 0; j < 2; j++) {
                const int col = c0 + wc * 32 + j * 16;
                wmma::store_matrix_sync(out + ((size_t)b * S + row) * D + col,
                                        acc[i][j], D, wmma::mem_row_major);
            }
        }
        #undef LOAD_CHUNK
    }
}

// ---------------------------------------------------------------------------
extern "C" void kernel_launch(void* const* d_in, const int* in_sizes, int n_in,
                              void* d_out, int out_size)
{
    const float* x         = (const float*)d_in[0];
    const float* q_weight  = (const float*)d_in[1];
    const float* q_bias    = (const float*)d_in[2];
    const float* k_weight  = (const float*)d_in[3];
    const float* attn_bias = (const float*)d_in[4];

    float* out  = (float*)d_out;                       // [B,S,D]
    float* attn = (float*)d_out + (size_t)B * S * D;   // [B,S,S]

    cudaFuncSetAttribute(logits_mma, cudaFuncAttributeMaxDynamicSharedMemorySize, 141312);
    cudaFuncSetAttribute(out_mma,    cudaFuncAttributeMaxDynamicSharedMemorySize, 110592);

    proj_kernel<<<S, 256>>>(x, q_weight, q_bias, k_weight);

    xsplit_kernel<<<dim3(S / 32, D / 32, B), dim3(32, 8)>>>(x);

    logits_mma<<<128, 256, 141312>>>(attn_bias, attn);

    out_mma<<<128, 256, 110592>>>(out);
}

// round 10
// speedup vs baseline: 2.7165x; 1.9879x over previous
#include <cuda_runtime.h>
#include <cuda_fp16.h>
#include <mma.h>
#include <cstddef>
#include <cstdint>

using namespace nvcuda;

#define B 16
#define S 1024
#define D 384
#define QK 64

__device__ __half g_Qh [(size_t)B * S * QK];
__device__ __half g_Kh [(size_t)B * S * QK];
__device__ __half g_XTh[(size_t)B * D * S];   // [b][c][m]
__device__ __half g_Ph [(size_t)B * S * S];   // softmax probs fp16

#define CP_ASYNC16(dst_u32, src_ptr) \
    asm volatile("cp.async.cg.shared.global [%0], [%1], 16;\n" :: "r"(dst_u32), "l"(src_ptr))
#define CP_COMMIT() asm volatile("cp.async.commit_group;\n" ::)
#define CP_WAIT2()  asm volatile("cp.async.wait_group 2;\n" ::)
#define CP_WAIT1()  asm volatile("cp.async.wait_group 1;\n" ::)
#define CP_WAIT0()  asm volatile("cp.async.wait_group 0;\n" ::)

#define PITCH 72                      // fp16 smem pitch (144B rows)
#define MAT_BYTES (128 * PITCH * 2)   // 18432
#define SPITCH 132                    // fp32 staging pitch (floats)

typedef wmma::fragment<wmma::matrix_a, 16, 16, 16, __half, wmma::row_major> FragA;
typedef wmma::fragment<wmma::matrix_b, 16, 16, 16, __half, wmma::col_major> FragB;
typedef wmma::fragment<wmma::accumulator, 16, 16, 16, float> FragC;

typedef wmma::fragment<wmma::matrix_a, 16, 16, 8, wmma::precision::tf32, wmma::row_major> TFragA;
typedef wmma::fragment<wmma::matrix_b, 16, 16, 8, wmma::precision::tf32, wmma::col_major> TFragB;
typedef wmma::fragment<wmma::accumulator, 16, 16, 8, float> TFragC;

// ---------------------------------------------------------------------------
// Kernel 1: proj via tf32 wmma. Grid=1024 (one n per block), 256 thr.
// A = x[:, n, :] (16x384 fp32, resident), B = [qw[n]; kw[n]] (128x384),
// streamed in 6 k-chunks of 64 (double-buffered cp.async, raw fp32).
// Warp w owns output tile [16 x 16] at cols w*16. Epilogue: stage -> fp16.
// smem: A 16x392 f32 + 2 x 128x72 f32 + stage 16x132 f32 = 107264 B.
// ---------------------------------------------------------------------------
#define APITCH 392
#define BPITCH 72
#define PROJ_SMEM (16*APITCH*4 + 2*128*BPITCH*4 + 16*132*4)

__global__ __launch_bounds__(256) void proj_mma(
    const float* __restrict__ x, const float* __restrict__ qw,
    const float* __restrict__ qb, const float* __restrict__ kw)
{
    extern __shared__ float psm[];
    float* As    = psm;                      // 16 x 392
    float* Bs    = psm + 16 * APITCH;        // 2 x 128 x 72
    float* stage = Bs + 2 * 128 * BPITCH;    // 16 x 132

    const int n = blockIdx.x;
    const int tid = threadIdx.x;
    const uint32_t smA = (uint32_t)__cvta_generic_to_shared(As);
    const uint32_t smB = (uint32_t)__cvta_generic_to_shared(Bs);

    // A: 16 rows x 96 x 16B chunks = 1536
    const float* xp = x + (size_t)n * D;
    #pragma unroll
    for (int i = 0; i < 6; i++) {
        int g = tid + 256 * i;
        int r = g / 96, c = g % 96;
        CP_ASYNC16(smA + (uint32_t)(r * APITCH + c * 4) * 4u,
                   xp + (size_t)r * S * D + c * 4);
    }

    // W chunk loader: 128 rows x 16 x 16B = 2048 chunks
    #define LOAD_W(kc_, buf_) do { \
        const uint32_t bb_ = smB + (uint32_t)(buf_) * (128u * BPITCH * 4u); \
        _Pragma("unroll") \
        for (int i = 0; i < 8; i++) { \
            int g = tid + 256 * i; \
            int r = g >> 4, c = g & 15; \
            const float* src_ = (r < 64) \
                ? (qw + ((size_t)n * QK + r) * D) \
                : (kw + ((size_t)n * QK + (r - 64)) * D); \
            CP_ASYNC16(bb_ + (uint32_t)(r * BPITCH + c * 4) * 4u, \
                       src_ + (kc_) * 64 + c * 4); \
        } \
    } while (0)

    LOAD_W(0, 0); CP_COMMIT();   // group 0 (includes A)
    LOAD_W(1, 1); CP_COMMIT();   // group 1

    const int wid = tid >> 5;
    TFragC cacc;
    wmma::fill_fragment(cacc, 0.0f);

    for (int kc = 0; kc < 6; kc++) {
        if (kc < 5) CP_WAIT1(); else CP_WAIT0();
        __syncthreads();

        const float* buf = Bs + (size_t)(kc & 1) * 128 * BPITCH;
        #pragma unroll
        for (int ks = 0; ks < 8; ks++) {
            TFragA a;
            TFragB bfr;
            wmma::load_matrix_sync(a, As + kc * 64 + ks * 8, APITCH);
            wmma::load_matrix_sync(bfr, buf + (size_t)(wid * 16) * BPITCH + ks * 8, BPITCH);
            #pragma unroll
            for (int t = 0; t < a.num_elements; t++) a.x[t] = wmma::__float_to_tf32(a.x[t]);
            #pragma unroll
            for (int t = 0; t < bfr.num_elements; t++) bfr.x[t] = wmma::__float_to_tf32(bfr.x[t]);
            wmma::mma_sync(cacc, a, bfr, cacc);
        }
        __syncthreads();
        if (kc + 2 < 6) { LOAD_W(kc + 2, kc & 1); CP_COMMIT(); }
    }

    wmma::store_matrix_sync(stage + wid * 16, cacc, 132, wmma::mem_row_major);
    __syncthreads();

    const float scale = 0.05103103630798287f;  // 384^-0.5
    #pragma unroll
    for (int i = 0; i < 8; i++) {
        int g = tid + 256 * i;
        int b = g >> 7, d = g & 127;
        float v = stage[b * 132 + d];
        if (d < QK)
            g_Qh[((size_t)b * S + n) * QK + d] = __float2half_rn(scale * (v + qb[n * QK + d]));
        else
            g_Kh[((size_t)b * S + n) * QK + (d - QK)] = __float2half_rn(v);
    }
    #undef LOAD_W
}

// ---------------------------------------------------------------------------
// Kernel 1b: transpose x -> XT[b][c][m] fp16
// ---------------------------------------------------------------------------
__global__ __launch_bounds__(256) void xsplit_kernel(const float* __restrict__ x)
{
    __shared__ float tb[32][33];
    const int b = blockIdx.z, m0 = blockIdx.x * 32, c0 = blockIdx.y * 32;
    const int tx = threadIdx.x, ty = threadIdx.y;

    #pragma unroll
    for (int j = 0; j < 4; j++)
        tb[ty + 8 * j][tx] = x[((size_t)b * S + m0 + ty + 8 * j) * D + c0 + tx];
    __syncthreads();
    #pragma unroll
    for (int j = 0; j < 4; j++) {
        float v = tb[tx][ty + 8 * j];
        size_t o = ((size_t)b * D + c0 + ty + 8 * j) * S + m0 + tx;
        g_XTh[o] = __float2half_rn(v);
    }
}

// ---------------------------------------------------------------------------
// Kernel 2: logits = Q @ K^T + bias, FUSED row softmax (unchanged from R9).
// ---------------------------------------------------------------------------
__global__ __launch_bounds__(256) void logits_mma(
    const float* __restrict__ attn_bias, float* __restrict__ attn)
{
    extern __shared__ __half sm[];
    __half* Qh = sm;
    float* stage = (float*)(sm + 4 * 128 * PITCH);

    const int tid = threadIdx.x;
    const int bx = blockIdx.x;
    const int nt = bx & 7, b = bx >> 3;
    const int n0 = nt * 128;

    const uint32_t smb = (uint32_t)__cvta_generic_to_shared(sm);
    const __half* qhp = g_Qh + ((size_t)b * S + n0) * QK;
    const __half* khp = g_Kh + (size_t)b * S * QK;

    #define LOAD_K(mt_, bufj_) do { \
        const uint32_t kb_ = smb + (uint32_t)(1 + (bufj_)) * MAT_BYTES; \
        const __half* kh_ = khp + (size_t)(mt_) * 128 * QK; \
        _Pragma("unroll") \
        for (int i = 0; i < 4; i++) { \
            int g = tid + 256 * i; \
            int r = g >> 3, c16 = g & 7; \
            CP_ASYNC16(kb_ + (uint32_t)(r * 144 + c16 * 16), kh_ + (size_t)r * QK + c16 * 8); \
        } \
    } while (0)

    #pragma unroll
    for (int i = 0; i < 4; i++) {
        int g = tid + 256 * i;
        int r = g >> 3, c16 = g & 7;
        CP_ASYNC16(smb + (uint32_t)(r * 144 + c16 * 16), qhp + (size_t)r * QK + c16 * 8);
    }
    LOAD_K(0, 0); CP_COMMIT();
    LOAD_K(1, 1); CP_COMMIT();

    const int wid = tid >> 5;
    const int lane = tid & 31;
    const int wn = wid >> 2;
    const int wm = wid & 3;

    for (int mt = 0; mt < 8; mt++) {
        __syncthreads();
        if (mt + 2 < 8) { LOAD_K(mt + 2, (mt + 2) % 3); CP_COMMIT(); }
        if (mt < 6)       CP_WAIT2();
        else if (mt == 6) CP_WAIT1();
        else              CP_WAIT0();
        __syncthreads();

        const __half* Kh = sm + (size_t)(1 + mt % 3) * 128 * PITCH;
        const int m0 = mt * 128;

        FragC acc[4][2];
        #pragma unroll
        for (int i = 0; i < 4; i++)
            #pragma unroll
            for (int j = 0; j < 2; j++) wmma::fill_fragment(acc[i][j], 0.0f);

        #pragma unroll
        for (int kk = 0; kk < 4; kk++) {
            FragA ah[4];
            FragB bh[2];
            #pragma unroll
            for (int i = 0; i < 4; i++) {
                int r = wn * 64 + i * 16;
                wmma::load_matrix_sync(ah[i], Qh + r * PITCH + kk * 16, PITCH);
            }
            #pragma unroll
            for (int j = 0; j < 2; j++) {
                int c = wm * 32 + j * 16;
                wmma::load_matrix_sync(bh[j], Kh + c * PITCH + kk * 16, PITCH);
            }
            #pragma unroll
            for (int i = 0; i < 4; i++)
                #pragma unroll
                for (int j = 0; j < 2; j++)
                    wmma::mma_sync(acc[i][j], ah[i], bh[j], acc[i][j]);
        }

        #pragma unroll
        for (int i = 0; i < 4; i++)
            #pragma unroll
            for (int j = 0; j < 2; j++)
                wmma::store_matrix_sync(
                    stage + (size_t)(wn * 64 + i * 16) * SPITCH + wm * 32 + j * 16,
                    acc[i][j], SPITCH, wmma::mem_row_major);
        __syncthreads();

        #pragma unroll
        for (int i = 0; i < 16; i++) {
            int g = tid + 256 * i;
            int r = g >> 5, c4 = (g & 31) * 4;
            float4 v = *(float4*)&stage[(size_t)r * SPITCH + c4];
            float4 bb = __ldg((const float4*)&attn_bias[(size_t)(n0 + r) * S + m0 + c4]);
            v.x += bb.x; v.y += bb.y; v.z += bb.z; v.w += bb.w;
            *(float4*)&attn[((size_t)b * S + n0 + r) * S + m0 + c4] = v;
        }
    }

    // fused softmax over this block's 128 rows
    __syncthreads();
    #pragma unroll 1
    for (int rr = 0; rr < 16; rr++) {
        const int r = wid * 16 + rr;
        float* rowp = attn + ((size_t)b * S + n0 + r) * S;
        __half* php = g_Ph + ((size_t)b * S + n0 + r) * S;

        float4 v[8];
        #pragma unroll
        for (int j = 0; j < 8; j++)
            v[j] = *(float4*)&rowp[j * 128 + lane * 4];

        float mx = -1e30f;
        #pragma unroll
        for (int j = 0; j < 8; j++)
            mx = fmaxf(mx, fmaxf(fmaxf(v[j].x, v[j].y), fmaxf(v[j].z, v[j].w)));
        #pragma unroll
        for (int o = 16; o > 0; o >>= 1) mx = fmaxf(mx, __shfl_xor_sync(0xffffffffu, mx, o));

        float ssum = 0.f;
        #pragma unroll
        for (int j = 0; j < 8; j++) {
            v[j].x = __expf(v[j].x - mx); v[j].y = __expf(v[j].y - mx);
            v[j].z = __expf(v[j].z - mx); v[j].w = __expf(v[j].w - mx);
            ssum += (v[j].x + v[j].y) + (v[j].z + v[j].w);
        }
        #pragma unroll
        for (int o = 16; o > 0; o >>= 1) ssum += __shfl_xor_sync(0xffffffffu, ssum, o);
        const float inv = 1.0f / ssum;

        #pragma unroll
        for (int j = 0; j < 8; j++) {
            float p0 = v[j].x * inv, p1 = v[j].y * inv;
            float p2 = v[j].z * inv, p3 = v[j].w * inv;
            float4 o4 = {p0, p1, p2, p3};
            *(float4*)&rowp[j * 128 + lane * 4] = o4;
            __half h0 = __float2half_rn(p0), h1 = __float2half_rn(p1);
            __half h2 = __float2half_rn(p2), h3 = __float2half_rn(p3);
            unsigned u0 = (unsigned)__half_as_ushort(h0) | ((unsigned)__half_as_ushort(h1) << 16);
            unsigned u1 = (unsigned)__half_as_ushort(h2) | ((unsigned)__half_as_ushort(h3) << 16);
            *(uint2*)&php[j * 128 + lane * 4] = make_uint2(u0, u1);
        }
    }
    #undef LOAD_K
}

// ---------------------------------------------------------------------------
// Kernel 4: out = P @ x. Grid=384 (b,nt,ct), 2-stage pipeline (73.7KB smem
// -> 2 CTA/SM), 16 K-chunks of 64, 2 matrices/chunk (P, XT).
// ---------------------------------------------------------------------------
__global__ __launch_bounds__(256) void out_mma(float* __restrict__ out)
{
    extern __shared__ __half sm[];

    const int tid = threadIdx.x;
    const int bx = blockIdx.x;
    const int ct = bx % 3;
    const int nt = (bx / 3) & 7;
    const int b  = bx / 24;
    const int n0 = nt * 128, c0 = ct * 128;

    const uint32_t smb = (uint32_t)__cvta_generic_to_shared(sm);
    const __half* aHp = g_Ph  + ((size_t)b * S + n0) * S;
    const __half* bHp = g_XTh + ((size_t)b * D + c0) * S;
    const __half* srcs[2] = {aHp, bHp};

    const int wid = tid >> 5;
    const int wn = wid >> 2;
    const int wc = wid & 3;

    #define LOAD_CHUNK(kc_, bufj_) do { \
        const int kof_ = (kc_) * 64; \
        const uint32_t bb_ = smb + (uint32_t)(bufj_) * (2u * MAT_BYTES); \
        _Pragma("unroll") \
        for (int mtx = 0; mtx < 2; mtx++) { \
            const __half* src = srcs[mtx] + kof_; \
            const uint32_t dst = bb_ + (uint32_t)mtx * MAT_BYTES; \
            _Pragma("unroll") \
            for (int i = 0; i < 4; i++) { \
                int g = tid + 256 * i; \
                int r = g >> 3, c16 = g & 7; \
                CP_ASYNC16(dst + (uint32_t)(r * 144 + c16 * 16), \
                           src + (size_t)r * S + c16 * 8); \
            } \
        } \
    } while (0)

    LOAD_CHUNK(0, 0); CP_COMMIT();

    FragC acc[4][2];
    #pragma unroll
    for (int i = 0; i < 4; i++)
        #pragma unroll
        for (int j = 0; j < 2; j++) wmma::fill_fragment(acc[i][j], 0.0f);

    for (int kc = 0; kc < 16; kc++) {
        if (kc < 15) { LOAD_CHUNK(kc + 1, (kc + 1) & 1); CP_COMMIT(); CP_WAIT1(); }
        else         { CP_WAIT0(); }
        __syncthreads();

        const __half* base = sm + (size_t)(kc & 1) * (2 * 128 * PITCH);
        const __half* Ah = base;
        const __half* Bh = base + 128 * PITCH;

        #pragma unroll
        for (int kk = 0; kk < 4; kk++) {
            FragA ah[4];
            FragB bh[2];
            #pragma unroll
            for (int i = 0; i < 4; i++) {
                int r = wn * 64 + i * 16;
                wmma::load_matrix_sync(ah[i], Ah + r * PITCH + kk * 16, PITCH);
            }
            #pragma unroll
            for (int j = 0; j < 2; j++) {
                int c = wc * 32 + j * 16;
                wmma::load_matrix_sync(bh[j], Bh + c * PITCH + kk * 16, PITCH);
            }
            #pragma unroll
            for (int i = 0; i < 4; i++)
                #pragma unroll
                for (int j = 0; j < 2; j++)
                    wmma::mma_sync(acc[i][j], ah[i], bh[j], acc[i][j]);
        }
        __syncthreads();
    }

    #pragma unroll
    for (int i = 0; i < 4; i++) {
        const int row = n0 + wn * 64 + i * 16;
        #pragma unroll
        for (int j = 0; j < 2; j++) {
            const int col = c0 + wc * 32 + j * 16;
            wmma::store_matrix_sync(out + ((size_t)b * S + row) * D + col,
                                    acc[i][j], D, wmma::mem_row_major);
        }
    }
    #undef LOAD_CHUNK
}

// ---------------------------------------------------------------------------
extern "C" void kernel_launch(void* const* d_in, const int* in_sizes, int n_in,
                              void* d_out, int out_size)
{
    const float* x         = (const float*)d_in[0];
    const float* q_weight  = (const float*)d_in[1];
    const float* q_bias    = (const float*)d_in[2];
    const float* k_weight  = (const float*)d_in[3];
    const float* attn_bias = (const float*)d_in[4];

    float* out  = (float*)d_out;                       // [B,S,D]
    float* attn = (float*)d_out + (size_t)B * S * D;   // [B,S,S]

    cudaFuncSetAttribute(proj_mma,   cudaFuncAttributeMaxDynamicSharedMemorySize, PROJ_SMEM);
    cudaFuncSetAttribute(logits_mma, cudaFuncAttributeMaxDynamicSharedMemorySize, 141312);
    cudaFuncSetAttribute(out_mma,    cudaFuncAttributeMaxDynamicSharedMemorySize, 73728);

    proj_mma<<<S, 256, PROJ_SMEM>>>(x, q_weight, q_bias, k_weight);

    xsplit_kernel<<<dim3(S / 32, D / 32, B), dim3(32, 8)>>>(x);

    logits_mma<<<128, 256, 141312>>>(attn_bias, attn);

    out_mma<<<384, 256, 73728>>>(out);
}

// round 11
// speedup vs baseline: 2.8259x; 1.0403x over previous
#include <cuda_runtime.h>
#include <cuda_fp16.h>
#include <mma.h>
#include <cstddef>
#include <cstdint>

using namespace nvcuda;

#define B 16
#define S 1024
#define D 384
#define QK 64

__device__ __half g_Qh[(size_t)B * S * QK];
__device__ __half g_Kh[(size_t)B * S * QK];
__device__ __half g_Xh[(size_t)B * S * D];    // x in fp16, natural [b][m][c]
__device__ __half g_Ph[(size_t)B * S * S];    // softmax probs fp16

#define CP_ASYNC16(dst_u32, src_ptr) \
    asm volatile("cp.async.cg.shared.global [%0], [%1], 16;\n" :: "r"(dst_u32), "l"(src_ptr))
#define CP_COMMIT() asm volatile("cp.async.commit_group;\n" ::)
#define CP_WAIT2()  asm volatile("cp.async.wait_group 2;\n" ::)
#define CP_WAIT1()  asm volatile("cp.async.wait_group 1;\n" ::)
#define CP_WAIT0()  asm volatile("cp.async.wait_group 0;\n" ::)

#define PITCH 72                      // fp16 smem pitch for 64-col tiles (144B)
#define BPITCH16 136                  // fp16 smem pitch for 128-col tiles (272B)
#define KMAT_BYTES (128 * PITCH * 2)  // 18432
#define SPITCH 132

typedef wmma::fragment<wmma::matrix_a, 16, 16, 16, __half, wmma::row_major> FragA;
typedef wmma::fragment<wmma::matrix_b, 16, 16, 16, __half, wmma::col_major> FragB;
typedef wmma::fragment<wmma::matrix_b, 16, 16, 16, __half, wmma::row_major> FragBR;
typedef wmma::fragment<wmma::accumulator, 16, 16, 16, float> FragC;

typedef wmma::fragment<wmma::matrix_a, 16, 16, 8, wmma::precision::tf32, wmma::row_major> TFragA;
typedef wmma::fragment<wmma::matrix_b, 16, 16, 8, wmma::precision::tf32, wmma::col_major> TFragB;
typedef wmma::fragment<wmma::accumulator, 16, 16, 8, float> TFragC;

// ---------------------------------------------------------------------------
// Kernel 1: proj via tf32 wmma (unchanged from R10 win).
// ---------------------------------------------------------------------------
#define APITCH 392
#define WPITCH 72
#define PROJ_SMEM (16*APITCH*4 + 2*128*WPITCH*4 + 16*132*4)

__global__ __launch_bounds__(256) void proj_mma(
    const float* __restrict__ x, const float* __restrict__ qw,
    const float* __restrict__ qb, const float* __restrict__ kw)
{
    extern __shared__ float psm[];
    float* As    = psm;                      // 16 x 392
    float* Bs    = psm + 16 * APITCH;        // 2 x 128 x 72
    float* stage = Bs + 2 * 128 * WPITCH;    // 16 x 132

    const int n = blockIdx.x;
    const int tid = threadIdx.x;
    const uint32_t smA = (uint32_t)__cvta_generic_to_shared(As);
    const uint32_t smB = (uint32_t)__cvta_generic_to_shared(Bs);

    const float* xp = x + (size_t)n * D;
    #pragma unroll
    for (int i = 0; i < 6; i++) {
        int g = tid + 256 * i;
        int r = g / 96, c = g % 96;
        CP_ASYNC16(smA + (uint32_t)(r * APITCH + c * 4) * 4u,
                   xp + (size_t)r * S * D + c * 4);
    }

    #define LOAD_W(kc_, buf_) do { \
        const uint32_t bb_ = smB + (uint32_t)(buf_) * (128u * WPITCH * 4u); \
        _Pragma("unroll") \
        for (int i = 0; i < 8; i++) { \
            int g = tid + 256 * i; \
            int r = g >> 4, c = g & 15; \
            const float* src_ = (r < 64) \
                ? (qw + ((size_t)n * QK + r) * D) \
                : (kw + ((size_t)n * QK + (r - 64)) * D); \
            CP_ASYNC16(bb_ + (uint32_t)(r * WPITCH + c * 4) * 4u, \
                       src_ + (kc_) * 64 + c * 4); \
        } \
    } while (0)

    LOAD_W(0, 0); CP_COMMIT();
    LOAD_W(1, 1); CP_COMMIT();

    const int wid = tid >> 5;
    TFragC cacc;
    wmma::fill_fragment(cacc, 0.0f);

    for (int kc = 0; kc < 6; kc++) {
        if (kc < 5) CP_WAIT1(); else CP_WAIT0();
        __syncthreads();

        const float* buf = Bs + (size_t)(kc & 1) * 128 * WPITCH;
        #pragma unroll
        for (int ks = 0; ks < 8; ks++) {
            TFragA a;
            TFragB bfr;
            wmma::load_matrix_sync(a, As + kc * 64 + ks * 8, APITCH);
            wmma::load_matrix_sync(bfr, buf + (size_t)(wid * 16) * WPITCH + ks * 8, WPITCH);
            #pragma unroll
            for (int t = 0; t < a.num_elements; t++) a.x[t] = wmma::__float_to_tf32(a.x[t]);
            #pragma unroll
            for (int t = 0; t < bfr.num_elements; t++) bfr.x[t] = wmma::__float_to_tf32(bfr.x[t]);
            wmma::mma_sync(cacc, a, bfr, cacc);
        }
        __syncthreads();
        if (kc + 2 < 6) { LOAD_W(kc + 2, kc & 1); CP_COMMIT(); }
    }

    wmma::store_matrix_sync(stage + wid * 16, cacc, 132, wmma::mem_row_major);
    __syncthreads();

    const float scale = 0.05103103630798287f;
    #pragma unroll
    for (int i = 0; i < 8; i++) {
        int g = tid + 256 * i;
        int b = g >> 7, d = g & 127;
        float v = stage[b * 132 + d];
        if (d < QK)
            g_Qh[((size_t)b * S + n) * QK + d] = __float2half_rn(scale * (v + qb[n * QK + d]));
        else
            g_Kh[((size_t)b * S + n) * QK + (d - QK)] = __float2half_rn(v);
    }
    #undef LOAD_W
}

// ---------------------------------------------------------------------------
// Kernel 1b: straight fp32 -> fp16 convert of x (no transpose).
// 6291456 elems; 8 per thread.
// ---------------------------------------------------------------------------
__global__ __launch_bounds__(256) void xconv_kernel(const float* __restrict__ x)
{
    const size_t base = ((size_t)blockIdx.x * 256 + threadIdx.x) * 8;
    float4 v0 = *(const float4*)(x + base);
    float4 v1 = *(const float4*)(x + base + 4);
    __half2 h0 = __floats2half2_rn(v0.x, v0.y);
    __half2 h1 = __floats2half2_rn(v0.z, v0.w);
    __half2 h2 = __floats2half2_rn(v1.x, v1.y);
    __half2 h3 = __floats2half2_rn(v1.z, v1.w);
    uint4 o;
    o.x = *(uint32_t*)&h0; o.y = *(uint32_t*)&h1;
    o.z = *(uint32_t*)&h2; o.w = *(uint32_t*)&h3;
    *(uint4*)&g_Xh[base] = o;
}

// ---------------------------------------------------------------------------
// Kernel 2: logits + fused softmax. Grid=256 (b, nt of 64 rows), 128 thr
// (4 warps), 2 CTA/SM. Q (64x64) resident; 8 K-tiles (128x64) streamed
// through 3-buffer pipeline. Warp tile 64n x 32m.
// smem: Q 9216 + 3*18432 + stage 64*132*4 = 98304.
// ---------------------------------------------------------------------------
__global__ __launch_bounds__(128) void logits_mma(
    const float* __restrict__ attn_bias, float* __restrict__ attn)
{
    extern __shared__ __half sm[];
    __half* Qh = sm;                          // 64 x 72
    float* stage = (float*)(sm + 4608 + 27648); // after Q + 3 K bufs

    const int tid = threadIdx.x;
    const int bx = blockIdx.x;
    const int nt = bx & 15, b = bx >> 4;
    const int n0 = nt * 64;

    const uint32_t smb = (uint32_t)__cvta_generic_to_shared(sm);
    const __half* qhp = g_Qh + ((size_t)b * S + n0) * QK;
    const __half* khp = g_Kh + (size_t)b * S * QK;

    #define LOAD_K(mt_, bufj_) do { \
        const uint32_t kb_ = smb + 9216u + (uint32_t)(bufj_) * KMAT_BYTES; \
        const __half* kh_ = khp + (size_t)(mt_) * 128 * QK; \
        _Pragma("unroll") \
        for (int i = 0; i < 8; i++) { \
            int g = tid + 128 * i; \
            int r = g >> 3, c16 = g & 7; \
            CP_ASYNC16(kb_ + (uint32_t)(r * 144 + c16 * 16), kh_ + (size_t)r * QK + c16 * 8); \
        } \
    } while (0)

    #pragma unroll
    for (int i = 0; i < 4; i++) {
        int g = tid + 128 * i;
        int r = g >> 3, c16 = g & 7;
        CP_ASYNC16(smb + (uint32_t)(r * 144 + c16 * 16), qhp + (size_t)r * QK + c16 * 8);
    }
    LOAD_K(0, 0); CP_COMMIT();
    LOAD_K(1, 1); CP_COMMIT();

    const int wid = tid >> 5;    // 0..3 -> 32 m-cols each
    const int lane = tid & 31;

    for (int mt = 0; mt < 8; mt++) {
        __syncthreads();
        if (mt + 2 < 8) { LOAD_K(mt + 2, (mt + 2) % 3); CP_COMMIT(); }
        if (mt < 6)       CP_WAIT2();
        else if (mt == 6) CP_WAIT1();
        else              CP_WAIT0();
        __syncthreads();

        const __half* Kh = sm + 4608 + (size_t)(mt % 3) * 128 * PITCH;
        const int m0 = mt * 128;

        FragC acc[4][2];
        #pragma unroll
        for (int i = 0; i < 4; i++)
            #pragma unroll
            for (int j = 0; j < 2; j++) wmma::fill_fragment(acc[i][j], 0.0f);

        #pragma unroll
        for (int kk = 0; kk < 4; kk++) {
            FragA ah[4];
            FragB bh[2];
            #pragma unroll
            for (int i = 0; i < 4; i++)
                wmma::load_matrix_sync(ah[i], Qh + (i * 16) * PITCH + kk * 16, PITCH);
            #pragma unroll
            for (int j = 0; j < 2; j++)
                wmma::load_matrix_sync(bh[j], Kh + (wid * 32 + j * 16) * PITCH + kk * 16, PITCH);
            #pragma unroll
            for (int i = 0; i < 4; i++)
                #pragma unroll
                for (int j = 0; j < 2; j++)
                    wmma::mma_sync(acc[i][j], ah[i], bh[j], acc[i][j]);
        }

        #pragma unroll
        for (int i = 0; i < 4; i++)
            #pragma unroll
            for (int j = 0; j < 2; j++)
                wmma::store_matrix_sync(
                    stage + (size_t)(i * 16) * SPITCH + wid * 32 + j * 16,
                    acc[i][j], SPITCH, wmma::mem_row_major);
        __syncthreads();

        // coalesced bias add + raw-logit store: 64 rows x 32 float4
        #pragma unroll
        for (int i = 0; i < 16; i++) {
            int g = tid + 128 * i;
            int r = g >> 5, c4 = (g & 31) * 4;
            float4 v = *(float4*)&stage[(size_t)r * SPITCH + c4];
            float4 bb = __ldg((const float4*)&attn_bias[(size_t)(n0 + r) * S + m0 + c4]);
            v.x += bb.x; v.y += bb.y; v.z += bb.z; v.w += bb.w;
            *(float4*)&attn[((size_t)b * S + n0 + r) * S + m0 + c4] = v;
        }
    }

    // fused softmax: 4 warps x 16 rows
    __syncthreads();
    #pragma unroll 1
    for (int rr = 0; rr < 16; rr++) {
        const int r = wid * 16 + rr;
        float* rowp = attn + ((size_t)b * S + n0 + r) * S;
        __half* php = g_Ph + ((size_t)b * S + n0 + r) * S;

        float4 v[8];
        #pragma unroll
        for (int j = 0; j < 8; j++)
            v[j] = *(float4*)&rowp[j * 128 + lane * 4];

        float mx = -1e30f;
        #pragma unroll
        for (int j = 0; j < 8; j++)
            mx = fmaxf(mx, fmaxf(fmaxf(v[j].x, v[j].y), fmaxf(v[j].z, v[j].w)));
        #pragma unroll
        for (int o = 16; o > 0; o >>= 1) mx = fmaxf(mx, __shfl_xor_sync(0xffffffffu, mx, o));

        float ssum = 0.f;
        #pragma unroll
        for (int j = 0; j < 8; j++) {
            v[j].x = __expf(v[j].x - mx); v[j].y = __expf(v[j].y - mx);
            v[j].z = __expf(v[j].z - mx); v[j].w = __expf(v[j].w - mx);
            ssum += (v[j].x + v[j].y) + (v[j].z + v[j].w);
        }
        #pragma unroll
        for (int o = 16; o > 0; o >>= 1) ssum += __shfl_xor_sync(0xffffffffu, ssum, o);
        const float inv = 1.0f / ssum;

        #pragma unroll
        for (int j = 0; j < 8; j++) {
            float p0 = v[j].x * inv, p1 = v[j].y * inv;
            float p2 = v[j].z * inv, p3 = v[j].w * inv;
            float4 o4 = {p0, p1, p2, p3};
            *(float4*)&rowp[j * 128 + lane * 4] = o4;
            __half h0 = __float2half_rn(p0), h1 = __float2half_rn(p1);
            __half h2 = __float2half_rn(p2), h3 = __float2half_rn(p3);
            unsigned u0 = (unsigned)__half_as_ushort(h0) | ((unsigned)__half_as_ushort(h1) << 16);
            unsigned u1 = (unsigned)__half_as_ushort(h2) | ((unsigned)__half_as_ushort(h3) << 16);
            *(uint2*)&php[j * 128 + lane * 4] = make_uint2(u0, u1);
        }
    }
    #undef LOAD_K
}

// ---------------------------------------------------------------------------
// Kernel 4: out = P @ x. Grid=384 (b,nt,ct), 128 thr (4 warps),
// warp tile 64x64 (16 wmma / 8 frag loads). B from natural-layout Xh
// (row-major fragments). 2-stage pipeline, smem/buf: A 18432 + B 17408.
// total smem 71680 -> 3 CTA/SM.
// ---------------------------------------------------------------------------
#define OBUF_BYTES 35840
#define OBUF_HALF  17920

__global__ __launch_bounds__(128) void out_mma(float* __restrict__ out)
{
    extern __shared__ __half sm[];

    const int tid = threadIdx.x;
    const int bx = blockIdx.x;
    const int ct = bx % 3;
    const int nt = (bx / 3) & 7;
    const int b  = bx / 24;
    const int n0 = nt * 128, c0 = ct * 128;

    const uint32_t smb = (uint32_t)__cvta_generic_to_shared(sm);
    const __half* aHp = g_Ph + ((size_t)b * S + n0) * S;
    const __half* xp  = g_Xh + (size_t)b * S * D;

    const int wid = tid >> 5;
    const int wn = wid >> 1;     // 0..1
    const int wc = wid & 1;      // 0..1

    #define LOAD_CHUNK(kc_, bufj_) do { \
        const int kof_ = (kc_) * 64; \
        const uint32_t ab_ = smb + (uint32_t)(bufj_) * OBUF_BYTES; \
        const uint32_t xb_ = ab_ + 18432u; \
        _Pragma("unroll") \
        for (int i = 0; i < 8; i++) { \
            int g = tid + 128 * i; \
            int r = g >> 3, c16 = g & 7; \
            CP_ASYNC16(ab_ + (uint32_t)(r * 144 + c16 * 16), \
                       aHp + (size_t)r * S + kof_ + c16 * 8); \
        } \
        _Pragma("unroll") \
        for (int i = 0; i < 8; i++) { \
            int g = tid + 128 * i; \
            int r = g >> 4, c16 = g & 15; \
            CP_ASYNC16(xb_ + (uint32_t)(r * 272 + c16 * 16), \
                       xp + (size_t)(kof_ + r) * D + c0 + c16 * 8); \
        } \
    } while (0)

    LOAD_CHUNK(0, 0); CP_COMMIT();

    FragC acc[4][4];
    #pragma unroll
    for (int i = 0; i < 4; i++)
        #pragma unroll
        for (int j = 0; j < 4; j++) wmma::fill_fragment(acc[i][j], 0.0f);

    for (int kc = 0; kc < 16; kc++) {
        if (kc < 15) { LOAD_CHUNK(kc + 1, (kc + 1) & 1); CP_COMMIT(); CP_WAIT1(); }
        else         { CP_WAIT0(); }
        __syncthreads();

        const __half* Ah = sm + (size_t)(kc & 1) * OBUF_HALF;          // [128n][72]
        const __half* Bh = Ah + 9216;                                  // [64m][136]

        #pragma unroll
        for (int kk = 0; kk < 4; kk++) {
            FragA ah[4];
            FragBR bh[4];
            #pragma unroll
            for (int i = 0; i < 4; i++)
                wmma::load_matrix_sync(ah[i], Ah + (wn * 64 + i * 16) * PITCH + kk * 16, PITCH);
            #pragma unroll
            for (int j = 0; j < 4; j++)
                wmma::load_matrix_sync(bh[j], Bh + (kk * 16) * BPITCH16 + wc * 64 + j * 16, BPITCH16);
            #pragma unroll
            for (int i = 0; i < 4; i++)
                #pragma unroll
                for (int j = 0; j < 4; j++)
                    wmma::mma_sync(acc[i][j], ah[i], bh[j], acc[i][j]);
        }
        __syncthreads();
    }

    #pragma unroll
    for (int i = 0; i < 4; i++) {
        const int row = n0 + wn * 64 + i * 16;
        #pragma unroll
        for (int j = 0; j < 4; j++) {
            const int col = c0 + wc * 64 + j * 16;
            wmma::store_matrix_sync(out + ((size_t)b * S + row) * D + col,
                                    acc[i][j], D, wmma::mem_row_major);
        }
    }
    #undef LOAD_CHUNK
}

// ---------------------------------------------------------------------------
extern "C" void kernel_launch(void* const* d_in, const int* in_sizes, int n_in,
                              void* d_out, int out_size)
{
    const float* x         = (const float*)d_in[0];
    const float* q_weight  = (const float*)d_in[1];
    const float* q_bias    = (const float*)d_in[2];
    const float* k_weight  = (const float*)d_in[3];
    const float* attn_bias = (const float*)d_in[4];

    float* out  = (float*)d_out;                       // [B,S,D]
    float* attn = (float*)d_out + (size_t)B * S * D;   // [B,S,S]

    cudaFuncSetAttribute(proj_mma,   cudaFuncAttributeMaxDynamicSharedMemorySize, PROJ_SMEM);
    cudaFuncSetAttribute(logits_mma, cudaFuncAttributeMaxDynamicSharedMemorySize, 98304);
    cudaFuncSetAttribute(out_mma,    cudaFuncAttributeMaxDynamicSharedMemorySize, 71680);

    proj_mma<<<S, 256, PROJ_SMEM>>>(x, q_weight, q_bias, k_weight);

    xconv_kernel<<<(B * S * D) / (256 * 8), 256>>>(x);

    logits_mma<<<256, 128, 98304>>>(attn_bias, attn);

    out_mma<<<384, 128, 71680>>>(out);
}